// round 5
// baseline (speedup 1.0000x reference)
#include <cuda_runtime.h>
#include <math.h>

#define SQ 384
#define HDIM 768
#define NHEAD 12
#define DH 64
#define NC 24
#define QKW_I_STRIDE (NC*HDIM)   // 18432
#define OUT_I_STRIDE (NC*SQ)     // 9216

// ---------------- scratch (device globals; no allocation allowed) ----------
__device__ float g_Q[NHEAD*SQ*DH];
__device__ float g_K[NHEAD*SQ*DH];
__device__ float g_V[NHEAD*SQ*DH];
__device__ float g_kb[NHEAD*SQ];
__device__ float g_qkW[SQ*NC*HDIM];      // [i][c][e]
__device__ float g_OUT[SQ*NC*SQ];        // [i][c][j]
__device__ float g_C2C[NHEAD*SQ*SQ];     // [h][i][j]
__device__ float g_P[NHEAD*SQ*SQ];       // probs

__device__ __forceinline__ float2 ffma2(float2 a, float2 b, float2 c) {
    unsigned long long ua = *reinterpret_cast<unsigned long long*>(&a);
    unsigned long long ub = *reinterpret_cast<unsigned long long*>(&b);
    unsigned long long uc = *reinterpret_cast<unsigned long long*>(&c);
    unsigned long long ud;
    asm("fma.rn.f32x2 %0, %1, %2, %3;" : "=l"(ud) : "l"(ua), "l"(ub), "l"(uc));
    return *reinterpret_cast<float2*>(&ud);
}

__device__ __forceinline__ void mma_tf32(float* d, unsigned a0, unsigned a1,
                                         unsigned a2, unsigned a3,
                                         unsigned b0, unsigned b1) {
    asm volatile(
        "mma.sync.aligned.m16n8k8.row.col.f32.tf32.tf32.f32 "
        "{%0,%1,%2,%3}, {%4,%5,%6,%7}, {%8,%9}, {%0,%1,%2,%3};"
        : "+f"(d[0]), "+f"(d[1]), "+f"(d[2]), "+f"(d[3])
        : "r"(a0), "r"(a1), "r"(a2), "r"(a3), "r"(b0), "r"(b1));
}

__device__ __forceinline__ void cp16(void* dst_smem, const void* src_gmem) {
    unsigned d = (unsigned)__cvta_generic_to_shared(dst_smem);
    asm volatile("cp.async.ca.shared.global [%0], [%1], 16;" :: "r"(d), "l"(src_gmem));
}
__device__ __forceinline__ void cp_commit() {
    asm volatile("cp.async.commit_group;");
}
template <int N>
__device__ __forceinline__ void cp_wait() {
    asm volatile("cp.async.wait_group %0;" :: "n"(N));
}

// ================= K1: QKV projections ====================================
__global__ void k1_qkv(const float* __restrict__ hidden,
                       const float* __restrict__ Wq, const float* __restrict__ bq,
                       const float* __restrict__ Wk, const float* __restrict__ bk,
                       const float* __restrict__ Wv, const float* __restrict__ bv)
{
    __shared__ float2 A2[16*65];
    __shared__ float  Bs[16*64];
    int z = blockIdx.z;
    const float* W = (z==0) ? Wq : (z==1) ? Wk : Wv;
    const float* b = (z==0) ? bq : (z==1) ? bk : bv;
    float* outp    = (z==0) ? g_Q : (z==1) ? g_K : g_V;
    int h  = blockIdx.x;
    int i0 = blockIdx.y * 64;
    int tid = threadIdx.x;
    int ix = tid & 15, iy = tid >> 4;

    float2 acc[4][2];
    #pragma unroll
    for (int u = 0; u < 4; ++u) { acc[u][0] = make_float2(0.f,0.f); acc[u][1] = make_float2(0.f,0.f); }

    for (int k0 = 0; k0 < HDIM; k0 += 16) {
        __syncthreads();
        #pragma unroll
        for (int p = 0; p < 4; ++p) {
            int idx = tid + p*256;
            int kk = idx & 15, r = idx >> 4;
            float v = hidden[(i0 + r)*HDIM + k0 + kk];
            A2[kk*65 + r] = make_float2(v, v);
        }
        #pragma unroll
        for (int p = 0; p < 4; ++p) {
            int idx = tid + p*256;
            int nn = idx & 63, kk = idx >> 6;
            Bs[kk*64 + nn] = W[(k0 + kk)*HDIM + h*64 + nn];
        }
        __syncthreads();
        #pragma unroll
        for (int kk = 0; kk < 16; ++kk) {
            float2 b0 = *(const float2*)&Bs[kk*64 + ix*4];
            float2 b1 = *(const float2*)&Bs[kk*64 + ix*4 + 2];
            #pragma unroll
            for (int u = 0; u < 4; ++u) {
                float2 a = A2[kk*65 + iy*4 + u];
                acc[u][0] = ffma2(a, b0, acc[u][0]);
                acc[u][1] = ffma2(a, b1, acc[u][1]);
            }
        }
    }
    int nb = h*64 + ix*4;
    float b0 = b[nb], b1 = b[nb+1], b2 = b[nb+2], b3 = b[nb+3];
    #pragma unroll
    for (int u = 0; u < 4; ++u) {
        int i = i0 + iy*4 + u;
        float* o = outp + (h*SQ + i)*DH + ix*4;
        o[0] = acc[u][0].x + b0;
        o[1] = acc[u][0].y + b1;
        o[2] = acc[u][1].x + b2;
        o[3] = acc[u][1].y + b3;
    }
}

// ================= K1b: kb[h][j] = k[h,j,:].bpq_h =========================
__global__ void k1b_kb(const float* __restrict__ bpq)
{
    int h = blockIdx.x, j = threadIdx.x;
    const float* kp = g_K + (h*SQ + j)*DH;
    const float* bp = bpq + h*64;
    float s = 0.f;
    #pragma unroll 8
    for (int d = 0; d < DH; ++d) s += kp[d]*bp[d];
    g_kb[h*SQ + j] = s;
}

// ================= K2: qkW[i][c][e] =======================================
__global__ void k2_qkw(const float* __restrict__ Wpk, const float* __restrict__ Wpq)
{
    __shared__ float2 A2[64*33];
    __shared__ float  BsT[64*66];
    int c = blockIdx.z;
    int h = (c < 12) ? c : c - 12;
    const float* Asrc = (c < 12) ? g_Q : g_K;
    const float* Wp   = (c < 12) ? Wpk : Wpq;
    int e0 = blockIdx.x * 64;
    int i0 = blockIdx.y * 32;
    int tid = threadIdx.x;

    #pragma unroll
    for (int p = 0; p < 8; ++p) {
        int idx = tid + p*256;
        int dd = idx & 63, ii = idx >> 6;
        float v = Asrc[(h*SQ + i0 + ii)*DH + dd];
        A2[dd*33 + ii] = make_float2(v, v);
    }
    #pragma unroll
    for (int p = 0; p < 16; ++p) {
        int idx = tid + p*256;
        int dd = idx & 63, ee = idx >> 6;
        BsT[dd*66 + ee] = Wp[(e0 + ee)*HDIM + h*64 + dd];
    }
    __syncthreads();

    int dx = tid & 15, iy = tid >> 4;
    float2 acc[2][2];
    acc[0][0]=make_float2(0,0); acc[0][1]=make_float2(0,0);
    acc[1][0]=make_float2(0,0); acc[1][1]=make_float2(0,0);
    #pragma unroll 16
    for (int dd = 0; dd < 64; ++dd) {
        float2 a0 = A2[dd*33 + iy*2];
        float2 a1 = A2[dd*33 + iy*2 + 1];
        float2 b0 = *(const float2*)&BsT[dd*66 + dx*4];
        float2 b1 = *(const float2*)&BsT[dd*66 + dx*4 + 2];
        acc[0][0] = ffma2(a0, b0, acc[0][0]);
        acc[0][1] = ffma2(a0, b1, acc[0][1]);
        acc[1][0] = ffma2(a1, b0, acc[1][0]);
        acc[1][1] = ffma2(a1, b1, acc[1][1]);
    }
    #pragma unroll
    for (int r = 0; r < 2; ++r) {
        float* o = g_qkW + (size_t)(i0 + iy*2 + r)*QKW_I_STRIDE + c*HDIM + e0 + dx*4;
        *(float2*)o       = acc[r][0];
        *(float2*)(o + 2) = acc[r][1];
    }
}

// ================= K2b: c2c[h][i][j], single-sync ========================
__global__ void k2b_c2c()
{
    __shared__ float2 A2[64*33];     // [dd][ii 0..31]
    __shared__ float  Bs[64*66];     // [dd][jj 0..63]
    int h  = blockIdx.z;
    int i0 = blockIdx.y * 32;
    int j0 = blockIdx.x * 64;
    int tid = threadIdx.x;

    #pragma unroll
    for (int p = 0; p < 8; ++p) {
        int idx = tid + p*256;
        int dd = idx & 63, ii = idx >> 6;
        float v = g_Q[(h*SQ + i0 + ii)*DH + dd];
        A2[dd*33 + ii] = make_float2(v, v);
    }
    #pragma unroll
    for (int p = 0; p < 16; ++p) {
        int idx = tid + p*256;
        int dd = idx & 63, jj = idx >> 6;
        Bs[dd*66 + jj] = g_K[(h*SQ + j0 + jj)*DH + dd];
    }
    __syncthreads();

    int ix = tid & 15, iy = tid >> 4;
    float2 acc[2][2];
    acc[0][0]=make_float2(0,0); acc[0][1]=make_float2(0,0);
    acc[1][0]=make_float2(0,0); acc[1][1]=make_float2(0,0);
    #pragma unroll 16
    for (int dd = 0; dd < 64; ++dd) {
        float2 a0 = A2[dd*33 + iy*2];
        float2 a1 = A2[dd*33 + iy*2 + 1];
        float2 b0 = *(const float2*)&Bs[dd*66 + ix*4];
        float2 b1 = *(const float2*)&Bs[dd*66 + ix*4 + 2];
        acc[0][0] = ffma2(a0, b0, acc[0][0]);
        acc[0][1] = ffma2(a0, b1, acc[0][1]);
        acc[1][0] = ffma2(a1, b0, acc[1][0]);
        acc[1][1] = ffma2(a1, b1, acc[1][1]);
    }
    #pragma unroll
    for (int r = 0; r < 2; ++r) {
        float* o = g_C2C + ((size_t)h*SQ + i0 + iy*2 + r)*SQ + j0 + ix*4;
        *(float2*)o       = acc[r][0];
        *(float2*)(o + 2) = acc[r][1];
    }
}

// ================= K3: pos contraction, tf32 MMA + cp.async pipeline ======
// CTA (jh, i): OUT[i][c][jh*192 + j] = sum_e qkW[i][c][e] * pos[i][jh*192+j][e]
#define JW 192                   // j per CTA
#define APITCH 12                // [j][e] pitch (floats): 16B-aligned, bank-clean
#define ASTAGE (JW*APITCH)       // 2304 floats
#define BSTAGE (NC*APITCH)       // 288 floats
#define STAGES 4
#define NCH 96
#define EPITCH 196               // epilogue [c][j] pitch

__global__ void __launch_bounds__(128) k3_pos(const float* __restrict__ pos)
{
    __shared__ float As[STAGES*ASTAGE];   // 36.9KB (epilogue reuses: needs 24*196=4704)
    __shared__ float Bs[STAGES*BSTAGE];   // 4.6KB
    int jh = blockIdx.x;                  // 0..1
    int i  = blockIdx.y;
    int tid = threadIdx.x;                // 128
    int warp = tid >> 5, lane = tid & 31;
    int gid = lane >> 2, tig = lane & 3;
    int j0w = warp * 48;

    const float* posi = pos + (size_t)i * (SQ*HDIM) + (size_t)jh * JW * HDIM;
    const float* wsrc = g_qkW + (size_t)i * QKW_I_STRIDE;

    float acc[3][3][4];
    #pragma unroll
    for (int jt = 0; jt < 3; ++jt)
        #pragma unroll
        for (int ct = 0; ct < 3; ++ct)
            #pragma unroll
            for (int r = 0; r < 4; ++r) acc[jt][ct][r] = 0.f;

    // ---- issue one stage's loads ----
    auto issue = [&](int ch, int s) {
        int e0 = ch * 8;
        float* as = As + s*ASTAGE;
        float* bs = Bs + s*BSTAGE;
        #pragma unroll
        for (int p = 0; p < 3; ++p) {
            int idx = tid + p*128;
            int j = idx >> 1, q4 = idx & 1;
            cp16(as + j*APITCH + q4*4, posi + (size_t)j*HDIM + e0 + q4*4);
        }
        if (tid < 48) {
            int c = tid >> 1, q4 = tid & 1;
            cp16(bs + c*APITCH + q4*4, wsrc + (size_t)c*HDIM + e0 + q4*4);
        }
    };

    issue(0, 0); cp_commit();
    issue(1, 1); cp_commit();
    issue(2, 2); cp_commit();

    for (int ch = 0; ch < NCH; ++ch) {
        int s = ch & (STAGES-1);
        cp_wait<STAGES-2>();
        __syncthreads();
        if (ch + STAGES - 1 < NCH) issue(ch + STAGES - 1, (ch + STAGES - 1) & (STAGES-1));
        cp_commit();

        const float* a = As + s*ASTAGE;
        const float* b = Bs + s*BSTAGE;
        unsigned bf[3][2];
        #pragma unroll
        for (int ct = 0; ct < 3; ++ct) {
            bf[ct][0] = __float_as_uint(b[(ct*8 + gid)*APITCH + tig]);
            bf[ct][1] = __float_as_uint(b[(ct*8 + gid)*APITCH + tig + 4]);
        }
        #pragma unroll
        for (int jt = 0; jt < 3; ++jt) {
            int j = j0w + jt*16 + gid;
            unsigned a0 = __float_as_uint(a[ j   *APITCH + tig    ]);
            unsigned a1 = __float_as_uint(a[(j+8)*APITCH + tig    ]);
            unsigned a2 = __float_as_uint(a[ j   *APITCH + tig + 4]);
            unsigned a3 = __float_as_uint(a[(j+8)*APITCH + tig + 4]);
            #pragma unroll
            for (int ct = 0; ct < 3; ++ct)
                mma_tf32(acc[jt][ct], a0, a1, a2, a3, bf[ct][0], bf[ct][1]);
        }
    }

    // ---- epilogue: stage [c][j] in smem (reusing As), coalesced STG ----
    cp_wait<0>();
    __syncthreads();
    #pragma unroll
    for (int jt = 0; jt < 3; ++jt) {
        #pragma unroll
        for (int ct = 0; ct < 3; ++ct) {
            int j = j0w + jt*16 + gid;
            int c = ct*8 + tig*2;
            As[ c   *EPITCH + j    ] = acc[jt][ct][0];
            As[(c+1)*EPITCH + j    ] = acc[jt][ct][1];
            As[ c   *EPITCH + j + 8] = acc[jt][ct][2];
            As[(c+1)*EPITCH + j + 8] = acc[jt][ct][3];
        }
    }
    __syncthreads();
    float* o_base = g_OUT + (size_t)i * OUT_I_STRIDE + jh*JW;
    #pragma unroll
    for (int p = 0; p < 9; ++p) {
        int idx = tid + p*128;            // 24c * 48 float4 = 1152
        int c = idx / 48, j4 = (idx % 48) * 4;
        float4 v = *(const float4*)&As[c*EPITCH + j4];
        *(float4*)(o_base + c*SQ + j4) = v;
    }
}

// ================= KS: fused scores assembly + softmax ====================
// block (ib, h): 16 i-rows x full 384 j.
#define SPITCH 386
__global__ void __launch_bounds__(256) ks_fused(const float* __restrict__ mask)
{
    __shared__ float S[16*SPITCH];        // 24.7KB
    __shared__ float red2[16];
    int ib = blockIdx.x, h = blockIdx.y;
    int i0 = ib * 16;
    int tid = threadIdx.x;

    // phase A1: c2c + c2p + kb, scaled, + mask
    #pragma unroll
    for (int p = 0; p < 24; ++p) {
        int idx = tid + p*256;
        int ii = idx / 384, j = idx % 384;
        float v = g_C2C[((size_t)h*SQ + i0 + ii)*SQ + j]
                + g_OUT[(size_t)(i0 + ii)*OUT_I_STRIDE + h*SQ + j]
                + g_kb[h*SQ + j];
        S[ii*SPITCH + j] = v * 0.125f + mask[j];
    }
    __syncthreads();

    // phase A2: += p2c^T (strided gather from g_OUT, 16x16 tiles)
    {
        int ti = tid & 15, tj = tid >> 4;
        #pragma unroll
        for (int t = 0; t < 24; ++t) {
            int j = t*16 + tj;
            float v = g_OUT[(size_t)j*OUT_I_STRIDE + (12 + h)*SQ + i0 + ti];
            S[ti*SPITCH + j] += v * 0.125f;
        }
    }
    __syncthreads();

    // phase B: softmax per row (1 warp per row, 2 rows per warp)
    int warp = tid >> 5, lane = tid & 31;
    #pragma unroll
    for (int w2 = 0; w2 < 2; ++w2) {
        int il = warp*2 + w2;
        const float* srow = &S[il*SPITCH];
        float x[12];
        float m = -1e30f;
        #pragma unroll
        for (int t = 0; t < 12; ++t) { x[t] = srow[lane + t*32]; m = fmaxf(m, x[t]); }
        #pragma unroll
        for (int o = 16; o; o >>= 1) m = fmaxf(m, __shfl_xor_sync(0xffffffffu, m, o));
        float ss = 0.f;
        #pragma unroll
        for (int t = 0; t < 12; ++t) { x[t] = __expf(x[t] - m); ss += x[t]; }
        #pragma unroll
        for (int o = 16; o; o >>= 1) ss += __shfl_xor_sync(0xffffffffu, ss, o);
        float inv = 1.f / ss;
        float* prow = g_P + ((size_t)h*SQ + i0 + il)*SQ;
        #pragma unroll
        for (int t = 0; t < 12; ++t) prow[lane + t*32] = x[t] * inv;
    }
    (void)red2;
}

// ================= K5: context = P @ V, write output ======================
__global__ void k5_pv(float* __restrict__ out)
{
    __shared__ float2 A2[16*65];
    __shared__ float  Bs[16*64];
    int h  = blockIdx.y;
    int i0 = blockIdx.x * 64;
    int tid = threadIdx.x;
    int ix = tid & 15, iy = tid >> 4;

    float2 acc[4][2];
    #pragma unroll
    for (int u = 0; u < 4; ++u) { acc[u][0] = make_float2(0.f,0.f); acc[u][1] = make_float2(0.f,0.f); }

    for (int k0 = 0; k0 < SQ; k0 += 16) {
        __syncthreads();
        #pragma unroll
        for (int p = 0; p < 4; ++p) {
            int idx = tid + p*256;
            int kk = idx & 15, r = idx >> 4;
            float v = g_P[((size_t)h*SQ + i0 + r)*SQ + k0 + kk];
            A2[kk*65 + r] = make_float2(v, v);
        }
        #pragma unroll
        for (int p = 0; p < 4; ++p) {
            int idx = tid + p*256;
            int nn = idx & 63, kk = idx >> 6;
            Bs[kk*64 + nn] = g_V[(h*SQ + k0 + kk)*DH + nn];
        }
        __syncthreads();
        #pragma unroll
        for (int kk = 0; kk < 16; ++kk) {
            float2 b0 = *(const float2*)&Bs[kk*64 + ix*4];
            float2 b1 = *(const float2*)&Bs[kk*64 + ix*4 + 2];
            #pragma unroll
            for (int u = 0; u < 4; ++u) {
                float2 a = A2[kk*65 + iy*4 + u];
                acc[u][0] = ffma2(a, b0, acc[u][0]);
                acc[u][1] = ffma2(a, b1, acc[u][1]);
            }
        }
    }
    #pragma unroll
    for (int u = 0; u < 4; ++u) {
        int i = i0 + iy*4 + u;
        float* o = out + (size_t)i*HDIM + h*64 + ix*4;
        *(float2*)o       = acc[u][0];
        *(float2*)(o + 2) = acc[u][1];
    }
}

// ================= launch =================================================
extern "C" void kernel_launch(void* const* d_in, const int* in_sizes, int n_in,
                              void* d_out, int out_size)
{
    const float* hidden = (const float*)d_in[0];
    const float* mask   = (const float*)d_in[1];
    const float* pos    = (const float*)d_in[2];
    const float* Wq  = (const float*)d_in[3];
    const float* bq  = (const float*)d_in[4];
    const float* Wk  = (const float*)d_in[5];
    const float* bk  = (const float*)d_in[6];
    const float* Wv  = (const float*)d_in[7];
    const float* bv  = (const float*)d_in[8];
    const float* Wpk = (const float*)d_in[9];
    // d_in[10] = bpk: constant over j -> softmax-invariant -> cancels exactly
    const float* Wpq = (const float*)d_in[11];
    const float* bpq = (const float*)d_in[12];
    float* out = (float*)d_out;

    // k3_pos kept at 4th launch so the fixed ncu sample lands on it.
    k1_qkv<<<dim3(12, 6, 3), 256>>>(hidden, Wq, bq, Wk, bk, Wv, bv);
    k2_qkw<<<dim3(12, 12, 24), 256>>>(Wpk, Wpq);
    k1b_kb<<<12, 384>>>(bpq);
    k3_pos<<<dim3(2, 384), 128>>>(pos);
    k2b_c2c<<<dim3(6, 12, 12), 256>>>();
    ks_fused<<<dim3(24, 12), 256>>>(mask);
    k5_pv<<<dim3(6, 12), 256>>>(out);
}

// round 7
// speedup vs baseline: 1.3594x; 1.3594x over previous
#include <cuda_runtime.h>
#include <math.h>

#define SQ 384
#define HDIM 768
#define NHEAD 12
#define DH 64
#define NC 24
#define QKW_I_STRIDE (NC*HDIM)   // 18432
#define OUT_I_STRIDE (NC*SQ)     // 9216

// ---------------- scratch (device globals; no allocation allowed) ----------
__device__ float g_Q[NHEAD*SQ*DH];
__device__ float g_K[NHEAD*SQ*DH];
__device__ float g_V[NHEAD*SQ*DH];
__device__ float g_kb[NHEAD*SQ];
__device__ float g_qkW[SQ*NC*HDIM];      // [i][c][e]
__device__ float g_OUT[SQ*NC*SQ];        // [i][c][j]
__device__ float g_C2C[NHEAD*SQ*SQ];     // [h][i][j]
__device__ float g_P[NHEAD*SQ*SQ];       // probs

__device__ __forceinline__ float2 ffma2(float2 a, float2 b, float2 c) {
    unsigned long long ua = *reinterpret_cast<unsigned long long*>(&a);
    unsigned long long ub = *reinterpret_cast<unsigned long long*>(&b);
    unsigned long long uc = *reinterpret_cast<unsigned long long*>(&c);
    unsigned long long ud;
    asm("fma.rn.f32x2 %0, %1, %2, %3;" : "=l"(ud) : "l"(ua), "l"(ub), "l"(uc));
    return *reinterpret_cast<float2*>(&ud);
}

__device__ __forceinline__ void mma_tf32(float* d, unsigned a0, unsigned a1,
                                         unsigned a2, unsigned a3,
                                         unsigned b0, unsigned b1) {
    asm volatile(
        "mma.sync.aligned.m16n8k8.row.col.f32.tf32.tf32.f32 "
        "{%0,%1,%2,%3}, {%4,%5,%6,%7}, {%8,%9}, {%0,%1,%2,%3};"
        : "+f"(d[0]), "+f"(d[1]), "+f"(d[2]), "+f"(d[3])
        : "r"(a0), "r"(a1), "r"(a2), "r"(a3), "r"(b0), "r"(b1));
}

__device__ __forceinline__ void cp16(void* dst_smem, const void* src_gmem) {
    unsigned d = (unsigned)__cvta_generic_to_shared(dst_smem);
    asm volatile("cp.async.ca.shared.global [%0], [%1], 16;" :: "r"(d), "l"(src_gmem));
}
__device__ __forceinline__ void cp_commit() {
    asm volatile("cp.async.commit_group;");
}
template <int N>
__device__ __forceinline__ void cp_wait() {
    asm volatile("cp.async.wait_group %0;" :: "n"(N));
}

// ================= K1: QKV projections ====================================
__global__ void k1_qkv(const float* __restrict__ hidden,
                       const float* __restrict__ Wq, const float* __restrict__ bq,
                       const float* __restrict__ Wk, const float* __restrict__ bk,
                       const float* __restrict__ Wv, const float* __restrict__ bv)
{
    __shared__ float2 A2[16*65];
    __shared__ float  Bs[16*64];
    int z = blockIdx.z;
    const float* W = (z==0) ? Wq : (z==1) ? Wk : Wv;
    const float* b = (z==0) ? bq : (z==1) ? bk : bv;
    float* outp    = (z==0) ? g_Q : (z==1) ? g_K : g_V;
    int h  = blockIdx.x;
    int i0 = blockIdx.y * 64;
    int tid = threadIdx.x;
    int ix = tid & 15, iy = tid >> 4;

    float2 acc[4][2];
    #pragma unroll
    for (int u = 0; u < 4; ++u) { acc[u][0] = make_float2(0.f,0.f); acc[u][1] = make_float2(0.f,0.f); }

    for (int k0 = 0; k0 < HDIM; k0 += 16) {
        __syncthreads();
        #pragma unroll
        for (int p = 0; p < 4; ++p) {
            int idx = tid + p*256;
            int kk = idx & 15, r = idx >> 4;
            float v = hidden[(i0 + r)*HDIM + k0 + kk];
            A2[kk*65 + r] = make_float2(v, v);
        }
        #pragma unroll
        for (int p = 0; p < 4; ++p) {
            int idx = tid + p*256;
            int nn = idx & 63, kk = idx >> 6;
            Bs[kk*64 + nn] = W[(k0 + kk)*HDIM + h*64 + nn];
        }
        __syncthreads();
        #pragma unroll
        for (int kk = 0; kk < 16; ++kk) {
            float2 b0 = *(const float2*)&Bs[kk*64 + ix*4];
            float2 b1 = *(const float2*)&Bs[kk*64 + ix*4 + 2];
            #pragma unroll
            for (int u = 0; u < 4; ++u) {
                float2 a = A2[kk*65 + iy*4 + u];
                acc[u][0] = ffma2(a, b0, acc[u][0]);
                acc[u][1] = ffma2(a, b1, acc[u][1]);
            }
        }
    }
    int nb = h*64 + ix*4;
    float b0 = b[nb], b1 = b[nb+1], b2 = b[nb+2], b3 = b[nb+3];
    #pragma unroll
    for (int u = 0; u < 4; ++u) {
        int i = i0 + iy*4 + u;
        float* o = outp + (h*SQ + i)*DH + ix*4;
        o[0] = acc[u][0].x + b0;
        o[1] = acc[u][0].y + b1;
        o[2] = acc[u][1].x + b2;
        o[3] = acc[u][1].y + b3;
    }
}

// ================= K1b: kb[h][j] = k[h,j,:].bpq_h =========================
__global__ void k1b_kb(const float* __restrict__ bpq)
{
    int h = blockIdx.x, j = threadIdx.x;
    const float* kp = g_K + (h*SQ + j)*DH;
    const float* bp = bpq + h*64;
    float s = 0.f;
    #pragma unroll 8
    for (int d = 0; d < DH; ++d) s += kp[d]*bp[d];
    g_kb[h*SQ + j] = s;
}

// ================= K2: qkW[i][c][e] =======================================
__global__ void k2_qkw(const float* __restrict__ Wpk, const float* __restrict__ Wpq)
{
    __shared__ float2 A2[64*33];
    __shared__ float  BsT[64*66];
    int c = blockIdx.z;
    int h = (c < 12) ? c : c - 12;
    const float* Asrc = (c < 12) ? g_Q : g_K;
    const float* Wp   = (c < 12) ? Wpk : Wpq;
    int e0 = blockIdx.x * 64;
    int i0 = blockIdx.y * 32;
    int tid = threadIdx.x;

    #pragma unroll
    for (int p = 0; p < 8; ++p) {
        int idx = tid + p*256;
        int dd = idx & 63, ii = idx >> 6;
        float v = Asrc[(h*SQ + i0 + ii)*DH + dd];
        A2[dd*33 + ii] = make_float2(v, v);
    }
    #pragma unroll
    for (int p = 0; p < 16; ++p) {
        int idx = tid + p*256;
        int dd = idx & 63, ee = idx >> 6;
        BsT[dd*66 + ee] = Wp[(e0 + ee)*HDIM + h*64 + dd];
    }
    __syncthreads();

    int dx = tid & 15, iy = tid >> 4;
    float2 acc[2][2];
    acc[0][0]=make_float2(0,0); acc[0][1]=make_float2(0,0);
    acc[1][0]=make_float2(0,0); acc[1][1]=make_float2(0,0);
    #pragma unroll 16
    for (int dd = 0; dd < 64; ++dd) {
        float2 a0 = A2[dd*33 + iy*2];
        float2 a1 = A2[dd*33 + iy*2 + 1];
        float2 b0 = *(const float2*)&BsT[dd*66 + dx*4];
        float2 b1 = *(const float2*)&BsT[dd*66 + dx*4 + 2];
        acc[0][0] = ffma2(a0, b0, acc[0][0]);
        acc[0][1] = ffma2(a0, b1, acc[0][1]);
        acc[1][0] = ffma2(a1, b0, acc[1][0]);
        acc[1][1] = ffma2(a1, b1, acc[1][1]);
    }
    #pragma unroll
    for (int r = 0; r < 2; ++r) {
        float* o = g_qkW + (size_t)(i0 + iy*2 + r)*QKW_I_STRIDE + c*HDIM + e0 + dx*4;
        *(float2*)o       = acc[r][0];
        *(float2*)(o + 2) = acc[r][1];
    }
}

// ================= K2b: c2c[h][i][j], single-sync ========================
__global__ void k2b_c2c()
{
    __shared__ float2 A2[64*33];     // [dd][ii 0..31]
    __shared__ float  Bs[64*66];     // [dd][jj 0..63]
    int h  = blockIdx.z;
    int i0 = blockIdx.y * 32;
    int j0 = blockIdx.x * 64;
    int tid = threadIdx.x;

    #pragma unroll
    for (int p = 0; p < 8; ++p) {
        int idx = tid + p*256;
        int dd = idx & 63, ii = idx >> 6;
        float v = g_Q[(h*SQ + i0 + ii)*DH + dd];
        A2[dd*33 + ii] = make_float2(v, v);
    }
    #pragma unroll
    for (int p = 0; p < 16; ++p) {
        int idx = tid + p*256;
        int dd = idx & 63, jj = idx >> 6;
        Bs[dd*66 + jj] = g_K[(h*SQ + j0 + jj)*DH + dd];
    }
    __syncthreads();

    int ix = tid & 15, iy = tid >> 4;
    float2 acc[2][2];
    acc[0][0]=make_float2(0,0); acc[0][1]=make_float2(0,0);
    acc[1][0]=make_float2(0,0); acc[1][1]=make_float2(0,0);
    #pragma unroll 16
    for (int dd = 0; dd < 64; ++dd) {
        float2 a0 = A2[dd*33 + iy*2];
        float2 a1 = A2[dd*33 + iy*2 + 1];
        float2 b0 = *(const float2*)&Bs[dd*66 + ix*4];
        float2 b1 = *(const float2*)&Bs[dd*66 + ix*4 + 2];
        acc[0][0] = ffma2(a0, b0, acc[0][0]);
        acc[0][1] = ffma2(a0, b1, acc[0][1]);
        acc[1][0] = ffma2(a1, b0, acc[1][0]);
        acc[1][1] = ffma2(a1, b1, acc[1][1]);
    }
    #pragma unroll
    for (int r = 0; r < 2; ++r) {
        float* o = g_C2C + ((size_t)h*SQ + i0 + iy*2 + r)*SQ + j0 + ix*4;
        *(float2*)o       = acc[r][0];
        *(float2*)(o + 2) = acc[r][1];
    }
}

// ================= K3: pos contraction, tf32 MMA, 128B-per-row chunks =====
// CTA (jb, i): OUT[i][c][jb*128 + j] = sum_e qkW[i][c][e] * pos[i][jb*128+j][e]
// e-chunk = 32 floats = one full 128B line per row. 24 chunks, 2-stage cp.async.
#define JW3 128                   // j rows per CTA
#define AP3 36                    // smem pitch (floats): 16B-aligned, bank-clean
#define ASTG (JW3*AP3)            // 4608 floats per stage
#define BSTG (NC*AP3)             // 864 floats per stage
#define NCH3 24                   // 768/32
#define EP3 132                   // epilogue [c][j] pitch

__global__ void __launch_bounds__(256, 5) k3_pos(const float* __restrict__ pos)
{
    __shared__ float As[2*ASTG];   // 36 KB (epilogue reuses: needs 24*132=3168)
    __shared__ float Bs[2*BSTG];   // 6.75 KB
    int jb = blockIdx.x;           // 0..2
    int i  = blockIdx.y;           // 0..383
    int tid = threadIdx.x;         // 256 = 8 warps
    int warp = tid >> 5, lane = tid & 31;
    int gid = lane >> 2, tig = lane & 3;
    int j0w = warp * 16;           // 16 j-rows per warp

    const float* posi = pos + (size_t)i * (SQ*HDIM) + (size_t)jb * JW3 * HDIM;
    const float* wsrc = g_qkW + (size_t)i * QKW_I_STRIDE;

    float acc[3][4];
    #pragma unroll
    for (int ct = 0; ct < 3; ++ct)
        #pragma unroll
        for (int r = 0; r < 4; ++r) acc[ct][r] = 0.f;

    auto issue = [&](int ch, int s) {
        int e0 = ch * 32;
        float* as = As + s*ASTG;
        float* bs = Bs + s*BSTG;
        #pragma unroll
        for (int p = 0; p < 4; ++p) {
            int idx = tid + p*256;         // 1024 = 128 rows * 8 x 16B
            int j = idx >> 3, q = idx & 7;
            cp16(as + j*AP3 + q*4, posi + (size_t)j*HDIM + e0 + q*4);
        }
        if (tid < 192) {                   // 24 c * 8 x 16B
            int c = tid >> 3, q = tid & 7;
            cp16(bs + c*AP3 + q*4, wsrc + (size_t)c*HDIM + e0 + q*4);
        }
    };

    issue(0, 0); cp_commit();

    for (int ch = 0; ch < NCH3; ++ch) {
        int s = ch & 1;
        if (ch + 1 < NCH3) {
            issue(ch + 1, s ^ 1); cp_commit();
            cp_wait<1>();                  // two pending: completes stage s
        } else {
            cp_wait<0>();                  // FINAL chunk: only stage s pending —
        }                                  // must drain fully (round-6 race fix)
        __syncthreads();                   // make stage s visible to all warps

        const float* a = As + s*ASTG;
        const float* b = Bs + s*BSTG;
        #pragma unroll
        for (int ks = 0; ks < 4; ++ks) {
            int eo = ks * 8;
            unsigned a0 = __float_as_uint(a[(j0w + gid    )*AP3 + eo + tig    ]);
            unsigned a1 = __float_as_uint(a[(j0w + gid + 8)*AP3 + eo + tig    ]);
            unsigned a2 = __float_as_uint(a[(j0w + gid    )*AP3 + eo + tig + 4]);
            unsigned a3 = __float_as_uint(a[(j0w + gid + 8)*AP3 + eo + tig + 4]);
            #pragma unroll
            for (int ct = 0; ct < 3; ++ct) {
                unsigned b0 = __float_as_uint(b[(ct*8 + gid)*AP3 + eo + tig    ]);
                unsigned b1 = __float_as_uint(b[(ct*8 + gid)*AP3 + eo + tig + 4]);
                mma_tf32(acc[ct], a0, a1, a2, a3, b0, b1);
            }
        }
        __syncthreads();                   // all reads of stage s done before reuse
    }

    // ---- epilogue: stage [c][j] in smem (reuse As), coalesced STG ----
    #pragma unroll
    for (int ct = 0; ct < 3; ++ct) {
        int c = ct*8 + tig*2;
        As[ c   *EP3 + j0w + gid    ] = acc[ct][0];
        As[(c+1)*EP3 + j0w + gid    ] = acc[ct][1];
        As[ c   *EP3 + j0w + gid + 8] = acc[ct][2];
        As[(c+1)*EP3 + j0w + gid + 8] = acc[ct][3];
    }
    __syncthreads();
    float* o_base = g_OUT + (size_t)i * OUT_I_STRIDE + jb*JW3;
    #pragma unroll
    for (int p = 0; p < 3; ++p) {
        int idx = tid + p*256;             // 24c * 32 float4 = 768
        int c = idx >> 5, j4 = (idx & 31) * 4;
        float4 v = *(const float4*)&As[c*EP3 + j4];
        *(float4*)(o_base + c*SQ + j4) = v;
    }
}

// ================= KS: fused scores assembly + softmax ====================
#define SPITCH 386
__global__ void __launch_bounds__(256) ks_fused(const float* __restrict__ mask)
{
    __shared__ float S[16*SPITCH];        // 24.7KB
    int ib = blockIdx.x, h = blockIdx.y;
    int i0 = ib * 16;
    int tid = threadIdx.x;

    // phase A1: c2c + c2p + kb, scaled, + mask
    #pragma unroll
    for (int p = 0; p < 24; ++p) {
        int idx = tid + p*256;
        int ii = idx / 384, j = idx % 384;
        float v = g_C2C[((size_t)h*SQ + i0 + ii)*SQ + j]
                + g_OUT[(size_t)(i0 + ii)*OUT_I_STRIDE + h*SQ + j]
                + g_kb[h*SQ + j];
        S[ii*SPITCH + j] = v * 0.125f + mask[j];
    }
    __syncthreads();

    // phase A2: += p2c^T (strided gather from g_OUT, 16x16 tiles)
    {
        int ti = tid & 15, tj = tid >> 4;
        #pragma unroll
        for (int t = 0; t < 24; ++t) {
            int j = t*16 + tj;
            float v = g_OUT[(size_t)j*OUT_I_STRIDE + (12 + h)*SQ + i0 + ti];
            S[ti*SPITCH + j] += v * 0.125f;
        }
    }
    __syncthreads();

    // phase B: softmax per row (2 rows per warp)
    int warp = tid >> 5, lane = tid & 31;
    #pragma unroll
    for (int w2 = 0; w2 < 2; ++w2) {
        int il = warp*2 + w2;
        const float* srow = &S[il*SPITCH];
        float x[12];
        float m = -1e30f;
        #pragma unroll
        for (int t = 0; t < 12; ++t) { x[t] = srow[lane + t*32]; m = fmaxf(m, x[t]); }
        #pragma unroll
        for (int o = 16; o; o >>= 1) m = fmaxf(m, __shfl_xor_sync(0xffffffffu, m, o));
        float ss = 0.f;
        #pragma unroll
        for (int t = 0; t < 12; ++t) { x[t] = __expf(x[t] - m); ss += x[t]; }
        #pragma unroll
        for (int o = 16; o; o >>= 1) ss += __shfl_xor_sync(0xffffffffu, ss, o);
        float inv = 1.f / ss;
        float* prow = g_P + ((size_t)h*SQ + i0 + il)*SQ;
        #pragma unroll
        for (int t = 0; t < 12; ++t) prow[lane + t*32] = x[t] * inv;
    }
}

// ================= K5: context = P @ V, write output ======================
__global__ void k5_pv(float* __restrict__ out)
{
    __shared__ float2 A2[16*65];
    __shared__ float  Bs[16*64];
    int h  = blockIdx.y;
    int i0 = blockIdx.x * 64;
    int tid = threadIdx.x;
    int ix = tid & 15, iy = tid >> 4;

    float2 acc[4][2];
    #pragma unroll
    for (int u = 0; u < 4; ++u) { acc[u][0] = make_float2(0.f,0.f); acc[u][1] = make_float2(0.f,0.f); }

    for (int k0 = 0; k0 < SQ; k0 += 16) {
        __syncthreads();
        #pragma unroll
        for (int p = 0; p < 4; ++p) {
            int idx = tid + p*256;
            int kk = idx & 15, r = idx >> 4;
            float v = g_P[((size_t)h*SQ + i0 + r)*SQ + k0 + kk];
            A2[kk*65 + r] = make_float2(v, v);
        }
        #pragma unroll
        for (int p = 0; p < 4; ++p) {
            int idx = tid + p*256;
            int nn = idx & 63, kk = idx >> 6;
            Bs[kk*64 + nn] = g_V[(h*SQ + k0 + kk)*DH + nn];
        }
        __syncthreads();
        #pragma unroll
        for (int kk = 0; kk < 16; ++kk) {
            float2 b0 = *(const float2*)&Bs[kk*64 + ix*4];
            float2 b1 = *(const float2*)&Bs[kk*64 + ix*4 + 2];
            #pragma unroll
            for (int u = 0; u < 4; ++u) {
                float2 a = A2[kk*65 + iy*4 + u];
                acc[u][0] = ffma2(a, b0, acc[u][0]);
                acc[u][1] = ffma2(a, b1, acc[u][1]);
            }
        }
    }
    #pragma unroll
    for (int u = 0; u < 4; ++u) {
        int i = i0 + iy*4 + u;
        float* o = out + (size_t)i*HDIM + h*64 + ix*4;
        *(float2*)o       = acc[u][0];
        *(float2*)(o + 2) = acc[u][1];
    }
}

// ================= launch =================================================
extern "C" void kernel_launch(void* const* d_in, const int* in_sizes, int n_in,
                              void* d_out, int out_size)
{
    const float* hidden = (const float*)d_in[0];
    const float* mask   = (const float*)d_in[1];
    const float* pos    = (const float*)d_in[2];
    const float* Wq  = (const float*)d_in[3];
    const float* bq  = (const float*)d_in[4];
    const float* Wk  = (const float*)d_in[5];
    const float* bk  = (const float*)d_in[6];
    const float* Wv  = (const float*)d_in[7];
    const float* bv  = (const float*)d_in[8];
    const float* Wpk = (const float*)d_in[9];
    // d_in[10] = bpk: constant over j -> softmax-invariant -> cancels exactly
    const float* Wpq = (const float*)d_in[11];
    const float* bpq = (const float*)d_in[12];
    float* out = (float*)d_out;

    // k3_pos kept at 4th launch so the fixed ncu sample lands on it.
    k1_qkv<<<dim3(12, 6, 3), 256>>>(hidden, Wq, bq, Wk, bk, Wv, bv);
    k2_qkw<<<dim3(12, 12, 24), 256>>>(Wpk, Wpq);
    k1b_kb<<<12, 384>>>(bpq);
    k3_pos<<<dim3(3, 384), 256>>>(pos);
    k2b_c2c<<<dim3(6, 12, 12), 256>>>();
    ks_fused<<<dim3(24, 12), 256>>>(mask);
    k5_pv<<<dim3(6, 12), 256>>>(out);
}

// round 8
// speedup vs baseline: 1.6222x; 1.1933x over previous
#include <cuda_runtime.h>
#include <math.h>

#define SQ 384
#define HDIM 768
#define NHEAD 12
#define DH 64
#define NC 24
#define QKW_I_STRIDE (NC*HDIM)   // 18432
#define OUT_I_STRIDE (NC*SQ)     // 9216

// ---------------- scratch (device globals; no allocation allowed) ----------
__device__ float g_Q[NHEAD*SQ*DH];
__device__ float g_K[NHEAD*SQ*DH];
__device__ float g_V[NHEAD*SQ*DH];
__device__ float g_kb[NHEAD*SQ];
__device__ float g_qkW[SQ*NC*HDIM];      // [i][c][e]
__device__ float g_OUT[SQ*NC*SQ];        // [i][c][j]
__device__ float g_C2C[NHEAD*SQ*SQ];     // [h][i][j]
__device__ float g_P[NHEAD*SQ*SQ];       // probs

__device__ __forceinline__ float2 ffma2(float2 a, float2 b, float2 c) {
    unsigned long long ua = *reinterpret_cast<unsigned long long*>(&a);
    unsigned long long ub = *reinterpret_cast<unsigned long long*>(&b);
    unsigned long long uc = *reinterpret_cast<unsigned long long*>(&c);
    unsigned long long ud;
    asm("fma.rn.f32x2 %0, %1, %2, %3;" : "=l"(ud) : "l"(ua), "l"(ub), "l"(uc));
    return *reinterpret_cast<float2*>(&ud);
}

__device__ __forceinline__ void mma_tf32(float* d, unsigned a0, unsigned a1,
                                         unsigned a2, unsigned a3,
                                         unsigned b0, unsigned b1) {
    asm volatile(
        "mma.sync.aligned.m16n8k8.row.col.f32.tf32.tf32.f32 "
        "{%0,%1,%2,%3}, {%4,%5,%6,%7}, {%8,%9}, {%0,%1,%2,%3};"
        : "+f"(d[0]), "+f"(d[1]), "+f"(d[2]), "+f"(d[3])
        : "r"(a0), "r"(a1), "r"(a2), "r"(a3), "r"(b0), "r"(b1));
}

__device__ __forceinline__ void cp16(void* dst_smem, const void* src_gmem) {
    unsigned d = (unsigned)__cvta_generic_to_shared(dst_smem);
    asm volatile("cp.async.ca.shared.global [%0], [%1], 16;" :: "r"(d), "l"(src_gmem));
}
__device__ __forceinline__ void cp_commit() {
    asm volatile("cp.async.commit_group;");
}
template <int N>
__device__ __forceinline__ void cp_wait() {
    asm volatile("cp.async.wait_group %0;" :: "n"(N));
}

// ================= K1: QKV projections ====================================
__global__ void k1_qkv(const float* __restrict__ hidden,
                       const float* __restrict__ Wq, const float* __restrict__ bq,
                       const float* __restrict__ Wk, const float* __restrict__ bk,
                       const float* __restrict__ Wv, const float* __restrict__ bv)
{
    __shared__ float2 A2[16*65];
    __shared__ float  Bs[16*64];
    int z = blockIdx.z;
    const float* W = (z==0) ? Wq : (z==1) ? Wk : Wv;
    const float* b = (z==0) ? bq : (z==1) ? bk : bv;
    float* outp    = (z==0) ? g_Q : (z==1) ? g_K : g_V;
    int h  = blockIdx.x;
    int i0 = blockIdx.y * 64;
    int tid = threadIdx.x;
    int ix = tid & 15, iy = tid >> 4;

    float2 acc[4][2];
    #pragma unroll
    for (int u = 0; u < 4; ++u) { acc[u][0] = make_float2(0.f,0.f); acc[u][1] = make_float2(0.f,0.f); }

    for (int k0 = 0; k0 < HDIM; k0 += 16) {
        __syncthreads();
        #pragma unroll
        for (int p = 0; p < 4; ++p) {
            int idx = tid + p*256;
            int kk = idx & 15, r = idx >> 4;
            float v = hidden[(i0 + r)*HDIM + k0 + kk];
            A2[kk*65 + r] = make_float2(v, v);
        }
        #pragma unroll
        for (int p = 0; p < 4; ++p) {
            int idx = tid + p*256;
            int nn = idx & 63, kk = idx >> 6;
            Bs[kk*64 + nn] = W[(k0 + kk)*HDIM + h*64 + nn];
        }
        __syncthreads();
        #pragma unroll
        for (int kk = 0; kk < 16; ++kk) {
            float2 b0 = *(const float2*)&Bs[kk*64 + ix*4];
            float2 b1 = *(const float2*)&Bs[kk*64 + ix*4 + 2];
            #pragma unroll
            for (int u = 0; u < 4; ++u) {
                float2 a = A2[kk*65 + iy*4 + u];
                acc[u][0] = ffma2(a, b0, acc[u][0]);
                acc[u][1] = ffma2(a, b1, acc[u][1]);
            }
        }
    }
    int nb = h*64 + ix*4;
    float b0 = b[nb], b1 = b[nb+1], b2 = b[nb+2], b3 = b[nb+3];
    #pragma unroll
    for (int u = 0; u < 4; ++u) {
        int i = i0 + iy*4 + u;
        float* o = outp + (h*SQ + i)*DH + ix*4;
        o[0] = acc[u][0].x + b0;
        o[1] = acc[u][0].y + b1;
        o[2] = acc[u][1].x + b2;
        o[3] = acc[u][1].y + b3;
    }
}

// ================= K1b: kb[h][j] = k[h,j,:].bpq_h =========================
__global__ void k1b_kb(const float* __restrict__ bpq)
{
    int h = blockIdx.x, j = threadIdx.x;
    const float* kp = g_K + (h*SQ + j)*DH;
    const float* bp = bpq + h*64;
    float s = 0.f;
    #pragma unroll 8
    for (int d = 0; d < DH; ++d) s += kp[d]*bp[d];
    g_kb[h*SQ + j] = s;
}

// ================= K2: qkW[i][c][e] on tensor cores (tf32) ================
// CTA (eb, ib, c): qkW[i0+0..63][c][e0+0..63] = sum_d A[i][d]*B[e][d]
//   A = Q or K rows (row-major d);  B = Wp rows e, cols h*64+d (row-major d)
#define K2P 68    // smem pitch (floats); 68 mod 32 == 4 -> conflict-free frags
__global__ void __launch_bounds__(256) k2_qkw(const float* __restrict__ Wpk,
                                              const float* __restrict__ Wpq)
{
    __shared__ float As[64*K2P];    // [i][d]   17.4 KB
    __shared__ float Bs2[64*K2P];   // [e][d]   17.4 KB
    int eb = blockIdx.x;            // 0..11
    int ib = blockIdx.y;            // 0..5
    int c  = blockIdx.z;            // 0..23
    int h  = (c < 12) ? c : c - 12;
    const float* Asrc = (c < 12) ? g_Q : g_K;
    const float* Wp   = (c < 12) ? Wpk : Wpq;
    int i0 = ib * 64, e0 = eb * 64;
    int tid = threadIdx.x;
    int warp = tid >> 5, lane = tid & 31;
    int gid = lane >> 2, tig = lane & 3;
    int wy = warp >> 2;             // i-half (32 rows)
    int wx = warp & 3;              // e-quarter (16 cols)

    // loads (coalesced float4, one shot)
    #pragma unroll
    for (int p = 0; p < 4; ++p) {
        int idx = tid + p*256;
        int row = idx >> 4, q = idx & 15;
        float4 v = *(const float4*)(Asrc + (size_t)(h*SQ + i0 + row)*DH + q*4);
        *(float4*)&As[row*K2P + q*4] = v;
    }
    #pragma unroll
    for (int p = 0; p < 4; ++p) {
        int idx = tid + p*256;
        int row = idx >> 4, q = idx & 15;
        float4 v = *(const float4*)(Wp + (size_t)(e0 + row)*HDIM + h*64 + q*4);
        *(float4*)&Bs2[row*K2P + q*4] = v;
    }
    __syncthreads();

    float acc[2][2][4];
    #pragma unroll
    for (int mt = 0; mt < 2; ++mt)
        #pragma unroll
        for (int nt = 0; nt < 2; ++nt)
            #pragma unroll
            for (int r = 0; r < 4; ++r) acc[mt][nt][r] = 0.f;

    #pragma unroll
    for (int ks = 0; ks < 8; ++ks) {
        int eo = ks * 8;
        #pragma unroll
        for (int mt = 0; mt < 2; ++mt) {
            int m = wy*32 + mt*16;
            unsigned a0 = __float_as_uint(As[(m + gid    )*K2P + eo + tig    ]);
            unsigned a1 = __float_as_uint(As[(m + gid + 8)*K2P + eo + tig    ]);
            unsigned a2 = __float_as_uint(As[(m + gid    )*K2P + eo + tig + 4]);
            unsigned a3 = __float_as_uint(As[(m + gid + 8)*K2P + eo + tig + 4]);
            #pragma unroll
            for (int nt = 0; nt < 2; ++nt) {
                int n = wx*16 + nt*8;
                unsigned b0 = __float_as_uint(Bs2[(n + gid)*K2P + eo + tig    ]);
                unsigned b1 = __float_as_uint(Bs2[(n + gid)*K2P + eo + tig + 4]);
                mma_tf32(acc[mt][nt], a0, a1, a2, a3, b0, b1);
            }
        }
    }
    __syncthreads();

    // epilogue: stage [i][e] into As (reuse), then coalesced write
    #pragma unroll
    for (int mt = 0; mt < 2; ++mt) {
        #pragma unroll
        for (int nt = 0; nt < 2; ++nt) {
            int i = wy*32 + mt*16 + gid;
            int e = wx*16 + nt*8 + tig*2;
            *(float2*)&As[ i     *K2P + e] = make_float2(acc[mt][nt][0], acc[mt][nt][1]);
            *(float2*)&As[(i + 8)*K2P + e] = make_float2(acc[mt][nt][2], acc[mt][nt][3]);
        }
    }
    __syncthreads();
    #pragma unroll
    for (int p = 0; p < 4; ++p) {
        int idx = tid + p*256;
        int row = idx >> 4, q = idx & 15;
        float4 v = *(const float4*)&As[row*K2P + q*4];
        *(float4*)(g_qkW + (size_t)(i0 + row)*QKW_I_STRIDE + c*HDIM + e0 + q*4) = v;
    }
}

// ================= K2b: c2c[h][i][j], single-sync ========================
__global__ void k2b_c2c()
{
    __shared__ float2 A2[64*33];     // [dd][ii 0..31]
    __shared__ float  Bs[64*66];     // [dd][jj 0..63]
    int h  = blockIdx.z;
    int i0 = blockIdx.y * 32;
    int j0 = blockIdx.x * 64;
    int tid = threadIdx.x;

    #pragma unroll
    for (int p = 0; p < 8; ++p) {
        int idx = tid + p*256;
        int dd = idx & 63, ii = idx >> 6;
        float v = g_Q[(h*SQ + i0 + ii)*DH + dd];
        A2[dd*33 + ii] = make_float2(v, v);
    }
    #pragma unroll
    for (int p = 0; p < 16; ++p) {
        int idx = tid + p*256;
        int dd = idx & 63, jj = idx >> 6;
        Bs[dd*66 + jj] = g_K[(h*SQ + j0 + jj)*DH + dd];
    }
    __syncthreads();

    int ix = tid & 15, iy = tid >> 4;
    float2 acc[2][2];
    acc[0][0]=make_float2(0,0); acc[0][1]=make_float2(0,0);
    acc[1][0]=make_float2(0,0); acc[1][1]=make_float2(0,0);
    #pragma unroll 16
    for (int dd = 0; dd < 64; ++dd) {
        float2 a0 = A2[dd*33 + iy*2];
        float2 a1 = A2[dd*33 + iy*2 + 1];
        float2 b0 = *(const float2*)&Bs[dd*66 + ix*4];
        float2 b1 = *(const float2*)&Bs[dd*66 + ix*4 + 2];
        acc[0][0] = ffma2(a0, b0, acc[0][0]);
        acc[0][1] = ffma2(a0, b1, acc[0][1]);
        acc[1][0] = ffma2(a1, b0, acc[1][0]);
        acc[1][1] = ffma2(a1, b1, acc[1][1]);
    }
    #pragma unroll
    for (int r = 0; r < 2; ++r) {
        float* o = g_C2C + ((size_t)h*SQ + i0 + iy*2 + r)*SQ + j0 + ix*4;
        *(float2*)o       = acc[r][0];
        *(float2*)(o + 2) = acc[r][1];
    }
}

// ================= K3: pos contraction, tf32 MMA, 4-stage cp.async ========
// CTA (jb, i): OUT[i][c][jb*128 + j] = sum_e qkW[i][c][e] * pos[i][jb*128+j][e]
// e-chunk = 16, 48 chunks, 4 stages (lookahead 3), 1 barrier per chunk.
#define JW3 128                   // j rows per CTA
#define AP3 20                    // smem pitch (floats): 16B-aligned, bank-clean
#define ASTG (JW3*AP3)            // 2560 floats per stage
#define BSTG (NC*AP3)             // 480 floats per stage
#define NCH3 48                   // 768/16
#define EP3 132                   // epilogue [c][j] pitch

__global__ void __launch_bounds__(256, 4) k3_pos(const float* __restrict__ pos)
{
    __shared__ float As[4*ASTG];   // 40 KB (epilogue reuses first 3168 floats)
    __shared__ float Bs[4*BSTG];   // 7.5 KB
    int jb = blockIdx.x;           // 0..2
    int i  = blockIdx.y;           // 0..383
    int tid = threadIdx.x;         // 256 = 8 warps
    int warp = tid >> 5, lane = tid & 31;
    int gid = lane >> 2, tig = lane & 3;
    int j0w = warp * 16;           // 16 j-rows per warp

    const float* posi = pos + (size_t)i * (SQ*HDIM) + (size_t)jb * JW3 * HDIM;
    const float* wsrc = g_qkW + (size_t)i * QKW_I_STRIDE;

    float acc[3][4];
    #pragma unroll
    for (int ct = 0; ct < 3; ++ct)
        #pragma unroll
        for (int r = 0; r < 4; ++r) acc[ct][r] = 0.f;

    auto issue = [&](int ch, int s) {
        int e0 = ch * 16;
        float* as = As + s*ASTG;
        float* bs = Bs + s*BSTG;
        #pragma unroll
        for (int p = 0; p < 2; ++p) {
            int idx = tid + p*256;         // 512 = 128 rows * 4 x 16B
            int j = idx >> 2, q = idx & 3;
            cp16(as + j*AP3 + q*4, posi + (size_t)j*HDIM + e0 + q*4);
        }
        if (tid < 96) {                    // 24 c * 4 x 16B
            int c = tid >> 2, q = tid & 3;
            cp16(bs + c*AP3 + q*4, wsrc + (size_t)c*HDIM + e0 + q*4);
        }
    };

    issue(0, 0); cp_commit();
    issue(1, 1); cp_commit();
    issue(2, 2); cp_commit();

    for (int ch = 0; ch < NCH3; ++ch) {
        int s = ch & 3;
        // pending at this point: {ch, ch+1, ch+2} (fewer at tail)
        if      (ch < NCH3-2) cp_wait<2>();   // completes ch
        else if (ch == NCH3-2) cp_wait<1>();
        else                   cp_wait<0>();
        __syncthreads();                   // stage s visible; all warps past ch-1
        if (ch + 3 < NCH3) { issue(ch + 3, (ch + 3) & 3); cp_commit(); }

        const float* a = As + s*ASTG;
        const float* b = Bs + s*BSTG;
        #pragma unroll
        for (int ks = 0; ks < 2; ++ks) {
            int eo = ks * 8;
            unsigned a0 = __float_as_uint(a[(j0w + gid    )*AP3 + eo + tig    ]);
            unsigned a1 = __float_as_uint(a[(j0w + gid + 8)*AP3 + eo + tig    ]);
            unsigned a2 = __float_as_uint(a[(j0w + gid    )*AP3 + eo + tig + 4]);
            unsigned a3 = __float_as_uint(a[(j0w + gid + 8)*AP3 + eo + tig + 4]);
            #pragma unroll
            for (int ct = 0; ct < 3; ++ct) {
                unsigned b0 = __float_as_uint(b[(ct*8 + gid)*AP3 + eo + tig    ]);
                unsigned b1 = __float_as_uint(b[(ct*8 + gid)*AP3 + eo + tig + 4]);
                mma_tf32(acc[ct], a0, a1, a2, a3, b0, b1);
            }
        }
    }

    // ---- epilogue: stage [c][j] in smem (reuse As[0..3168)), coalesced STG
    // safe: As[0..3168) covers stages 0-1 (chunks 44/45), all reads complete.
    __syncthreads();
    #pragma unroll
    for (int ct = 0; ct < 3; ++ct) {
        int c = ct*8 + tig*2;
        As[ c   *EP3 + j0w + gid    ] = acc[ct][0];
        As[(c+1)*EP3 + j0w + gid    ] = acc[ct][1];
        As[ c   *EP3 + j0w + gid + 8] = acc[ct][2];
        As[(c+1)*EP3 + j0w + gid + 8] = acc[ct][3];
    }
    __syncthreads();
    float* o_base = g_OUT + (size_t)i * OUT_I_STRIDE + jb*JW3;
    #pragma unroll
    for (int p = 0; p < 3; ++p) {
        int idx = tid + p*256;             // 24c * 32 float4 = 768
        int c = idx >> 5, j4 = (idx & 31) * 4;
        float4 v = *(const float4*)&As[c*EP3 + j4];
        *(float4*)(o_base + c*SQ + j4) = v;
    }
}

// ================= KS: fused scores assembly + softmax ====================
#define SPITCH 386
__global__ void __launch_bounds__(256) ks_fused(const float* __restrict__ mask)
{
    __shared__ float S[16*SPITCH];        // 24.7KB
    int ib = blockIdx.x, h = blockIdx.y;
    int i0 = ib * 16;
    int tid = threadIdx.x;

    // phase A1: c2c + c2p + kb, scaled, + mask
    #pragma unroll
    for (int p = 0; p < 24; ++p) {
        int idx = tid + p*256;
        int ii = idx / 384, j = idx % 384;
        float v = g_C2C[((size_t)h*SQ + i0 + ii)*SQ + j]
                + g_OUT[(size_t)(i0 + ii)*OUT_I_STRIDE + h*SQ + j]
                + g_kb[h*SQ + j];
        S[ii*SPITCH + j] = v * 0.125f + mask[j];
    }
    __syncthreads();

    // phase A2: += p2c^T (strided gather from g_OUT, 16x16 tiles)
    {
        int ti = tid & 15, tj = tid >> 4;
        #pragma unroll
        for (int t = 0; t < 24; ++t) {
            int j = t*16 + tj;
            float v = g_OUT[(size_t)j*OUT_I_STRIDE + (12 + h)*SQ + i0 + ti];
            S[ti*SPITCH + j] += v * 0.125f;
        }
    }
    __syncthreads();

    // phase B: softmax per row (2 rows per warp)
    int warp = tid >> 5, lane = tid & 31;
    #pragma unroll
    for (int w2 = 0; w2 < 2; ++w2) {
        int il = warp*2 + w2;
        const float* srow = &S[il*SPITCH];
        float x[12];
        float m = -1e30f;
        #pragma unroll
        for (int t = 0; t < 12; ++t) { x[t] = srow[lane + t*32]; m = fmaxf(m, x[t]); }
        #pragma unroll
        for (int o = 16; o; o >>= 1) m = fmaxf(m, __shfl_xor_sync(0xffffffffu, m, o));
        float ss = 0.f;
        #pragma unroll
        for (int t = 0; t < 12; ++t) { x[t] = __expf(x[t] - m); ss += x[t]; }
        #pragma unroll
        for (int o = 16; o; o >>= 1) ss += __shfl_xor_sync(0xffffffffu, ss, o);
        float inv = 1.f / ss;
        float* prow = g_P + ((size_t)h*SQ + i0 + il)*SQ;
        #pragma unroll
        for (int t = 0; t < 12; ++t) prow[lane + t*32] = x[t] * inv;
    }
}

// ================= K5: context = P @ V, write output ======================
__global__ void k5_pv(float* __restrict__ out)
{
    __shared__ float2 A2[16*65];
    __shared__ float  Bs[16*64];
    int h  = blockIdx.y;
    int i0 = blockIdx.x * 64;
    int tid = threadIdx.x;
    int ix = tid & 15, iy = tid >> 4;

    float2 acc[4][2];
    #pragma unroll
    for (int u = 0; u < 4; ++u) { acc[u][0] = make_float2(0.f,0.f); acc[u][1] = make_float2(0.f,0.f); }

    for (int k0 = 0; k0 < SQ; k0 += 16) {
        __syncthreads();
        #pragma unroll
        for (int p = 0; p < 4; ++p) {
            int idx = tid + p*256;
            int kk = idx & 15, r = idx >> 4;
            float v = g_P[((size_t)h*SQ + i0 + r)*SQ + k0 + kk];
            A2[kk*65 + r] = make_float2(v, v);
        }
        #pragma unroll
        for (int p = 0; p < 4; ++p) {
            int idx = tid + p*256;
            int nn = idx & 63, kk = idx >> 6;
            Bs[kk*64 + nn] = g_V[(h*SQ + k0 + kk)*DH + nn];
        }
        __syncthreads();
        #pragma unroll
        for (int kk = 0; kk < 16; ++kk) {
            float2 b0 = *(const float2*)&Bs[kk*64 + ix*4];
            float2 b1 = *(const float2*)&Bs[kk*64 + ix*4 + 2];
            #pragma unroll
            for (int u = 0; u < 4; ++u) {
                float2 a = A2[kk*65 + iy*4 + u];
                acc[u][0] = ffma2(a, b0, acc[u][0]);
                acc[u][1] = ffma2(a, b1, acc[u][1]);
            }
        }
    }
    #pragma unroll
    for (int u = 0; u < 4; ++u) {
        int i = i0 + iy*4 + u;
        float* o = out + (size_t)i*HDIM + h*64 + ix*4;
        *(float2*)o       = acc[u][0];
        *(float2*)(o + 2) = acc[u][1];
    }
}

// ================= launch =================================================
extern "C" void kernel_launch(void* const* d_in, const int* in_sizes, int n_in,
                              void* d_out, int out_size)
{
    const float* hidden = (const float*)d_in[0];
    const float* mask   = (const float*)d_in[1];
    const float* pos    = (const float*)d_in[2];
    const float* Wq  = (const float*)d_in[3];
    const float* bq  = (const float*)d_in[4];
    const float* Wk  = (const float*)d_in[5];
    const float* bk  = (const float*)d_in[6];
    const float* Wv  = (const float*)d_in[7];
    const float* bv  = (const float*)d_in[8];
    const float* Wpk = (const float*)d_in[9];
    // d_in[10] = bpk: constant over j -> softmax-invariant -> cancels exactly
    const float* Wpq = (const float*)d_in[11];
    const float* bpq = (const float*)d_in[12];
    float* out = (float*)d_out;

    // k3_pos kept at 4th launch so the fixed ncu sample lands on it.
    k1_qkv<<<dim3(12, 6, 3), 256>>>(hidden, Wq, bq, Wk, bk, Wv, bv);
    k2_qkw<<<dim3(12, 6, 24), 256>>>(Wpk, Wpq);
    k1b_kb<<<12, 384>>>(bpq);
    k3_pos<<<dim3(3, 384), 256>>>(pos);
    k2b_c2c<<<dim3(6, 12, 12), 256>>>();
    ks_fused<<<dim3(24, 12), 256>>>(mask);
    k5_pv<<<dim3(6, 12), 256>>>(out);
}

// round 9
// speedup vs baseline: 1.6870x; 1.0399x over previous
#include <cuda_runtime.h>
#include <math.h>

#define SQ 384
#define HDIM 768
#define NHEAD 12
#define DH 64
#define NC 24
#define QKW_I_STRIDE (NC*HDIM)   // 18432
#define OUT_I_STRIDE (NC*SQ)     // 9216

// ---------------- scratch (device globals; no allocation allowed) ----------
__device__ float g_Q[NHEAD*SQ*DH];
__device__ float g_K[NHEAD*SQ*DH];
__device__ float g_V[NHEAD*SQ*DH];
__device__ float g_kb[NHEAD*SQ];
__device__ float g_qkW[SQ*NC*HDIM];      // [i][c][e]
__device__ float g_OUT[SQ*NC*SQ];        // [i][c][j]
__device__ float g_C2C[NHEAD*SQ*SQ];     // [h][i][j]
__device__ float g_P[NHEAD*SQ*SQ];       // probs

__device__ __forceinline__ float2 ffma2(float2 a, float2 b, float2 c) {
    unsigned long long ua = *reinterpret_cast<unsigned long long*>(&a);
    unsigned long long ub = *reinterpret_cast<unsigned long long*>(&b);
    unsigned long long uc = *reinterpret_cast<unsigned long long*>(&c);
    unsigned long long ud;
    asm("fma.rn.f32x2 %0, %1, %2, %3;" : "=l"(ud) : "l"(ua), "l"(ub), "l"(uc));
    return *reinterpret_cast<float2*>(&ud);
}

__device__ __forceinline__ void mma_tf32(float* d, unsigned a0, unsigned a1,
                                         unsigned a2, unsigned a3,
                                         unsigned b0, unsigned b1) {
    asm volatile(
        "mma.sync.aligned.m16n8k8.row.col.f32.tf32.tf32.f32 "
        "{%0,%1,%2,%3}, {%4,%5,%6,%7}, {%8,%9}, {%0,%1,%2,%3};"
        : "+f"(d[0]), "+f"(d[1]), "+f"(d[2]), "+f"(d[3])
        : "r"(a0), "r"(a1), "r"(a2), "r"(a3), "r"(b0), "r"(b1));
}

// split fp32 into tf32 hi + tf32 lo (3xTF32 error compensation)
__device__ __forceinline__ void split_tf32(float x, unsigned& hi, unsigned& lo) {
    unsigned h;
    asm("cvt.rna.tf32.f32 %0, %1;" : "=r"(h) : "f"(x));
    float r = x - __uint_as_float(h);
    unsigned l;
    asm("cvt.rna.tf32.f32 %0, %1;" : "=r"(l) : "f"(r));
    hi = h; lo = l;
}

__device__ __forceinline__ void cp16(void* dst_smem, const void* src_gmem) {
    unsigned d = (unsigned)__cvta_generic_to_shared(dst_smem);
    asm volatile("cp.async.ca.shared.global [%0], [%1], 16;" :: "r"(d), "l"(src_gmem));
}
__device__ __forceinline__ void cp_commit() {
    asm volatile("cp.async.commit_group;");
}
template <int N>
__device__ __forceinline__ void cp_wait() {
    asm volatile("cp.async.wait_group %0;" :: "n"(N));
}

// ================= K1: QKV projections ====================================
__global__ void k1_qkv(const float* __restrict__ hidden,
                       const float* __restrict__ Wq, const float* __restrict__ bq,
                       const float* __restrict__ Wk, const float* __restrict__ bk,
                       const float* __restrict__ Wv, const float* __restrict__ bv)
{
    __shared__ float2 A2[16*65];
    __shared__ float  Bs[16*64];
    int z = blockIdx.z;
    const float* W = (z==0) ? Wq : (z==1) ? Wk : Wv;
    const float* b = (z==0) ? bq : (z==1) ? bk : bv;
    float* outp    = (z==0) ? g_Q : (z==1) ? g_K : g_V;
    int h  = blockIdx.x;
    int i0 = blockIdx.y * 64;
    int tid = threadIdx.x;
    int ix = tid & 15, iy = tid >> 4;

    float2 acc[4][2];
    #pragma unroll
    for (int u = 0; u < 4; ++u) { acc[u][0] = make_float2(0.f,0.f); acc[u][1] = make_float2(0.f,0.f); }

    for (int k0 = 0; k0 < HDIM; k0 += 16) {
        __syncthreads();
        #pragma unroll
        for (int p = 0; p < 4; ++p) {
            int idx = tid + p*256;
            int kk = idx & 15, r = idx >> 4;
            float v = hidden[(i0 + r)*HDIM + k0 + kk];
            A2[kk*65 + r] = make_float2(v, v);
        }
        #pragma unroll
        for (int p = 0; p < 4; ++p) {
            int idx = tid + p*256;
            int nn = idx & 63, kk = idx >> 6;
            Bs[kk*64 + nn] = W[(k0 + kk)*HDIM + h*64 + nn];
        }
        __syncthreads();
        #pragma unroll
        for (int kk = 0; kk < 16; ++kk) {
            float2 b0 = *(const float2*)&Bs[kk*64 + ix*4];
            float2 b1 = *(const float2*)&Bs[kk*64 + ix*4 + 2];
            #pragma unroll
            for (int u = 0; u < 4; ++u) {
                float2 a = A2[kk*65 + iy*4 + u];
                acc[u][0] = ffma2(a, b0, acc[u][0]);
                acc[u][1] = ffma2(a, b1, acc[u][1]);
            }
        }
    }
    int nb = h*64 + ix*4;
    float b0 = b[nb], b1 = b[nb+1], b2 = b[nb+2], b3 = b[nb+3];
    #pragma unroll
    for (int u = 0; u < 4; ++u) {
        int i = i0 + iy*4 + u;
        float* o = outp + (h*SQ + i)*DH + ix*4;
        o[0] = acc[u][0].x + b0;
        o[1] = acc[u][0].y + b1;
        o[2] = acc[u][1].x + b2;
        o[3] = acc[u][1].y + b3;
    }
}

// ================= K1b: kb[h][j] = k[h,j,:].bpq_h =========================
__global__ void k1b_kb(const float* __restrict__ bpq)
{
    int h = blockIdx.x, j = threadIdx.x;
    const float* kp = g_K + (h*SQ + j)*DH;
    const float* bp = bpq + h*64;
    float s = 0.f;
    #pragma unroll 8
    for (int d = 0; d < DH; ++d) s += kp[d]*bp[d];
    g_kb[h*SQ + j] = s;
}

// ================= K2: qkW[i][c][e], 3xTF32 (error-compensated) ===========
// CTA (eb, ib, c): qkW[i0+0..63][c][e0+0..63] = sum_d A[i][d]*B[e][d]
#define K2P 68    // smem pitch (floats); 68 mod 32 == 4 -> conflict-free frags
__global__ void __launch_bounds__(256) k2_qkw(const float* __restrict__ Wpk,
                                              const float* __restrict__ Wpq)
{
    __shared__ float As[64*K2P];    // [i][d]
    __shared__ float Bs2[64*K2P];   // [e][d]
    int eb = blockIdx.x;            // 0..11
    int ib = blockIdx.y;            // 0..5
    int c  = blockIdx.z;            // 0..23
    int h  = (c < 12) ? c : c - 12;
    const float* Asrc = (c < 12) ? g_Q : g_K;
    const float* Wp   = (c < 12) ? Wpk : Wpq;
    int i0 = ib * 64, e0 = eb * 64;
    int tid = threadIdx.x;
    int warp = tid >> 5, lane = tid & 31;
    int gid = lane >> 2, tig = lane & 3;
    int wy = warp >> 2;             // i-half (32 rows)
    int wx = warp & 3;              // e-quarter (16 cols)

    #pragma unroll
    for (int p = 0; p < 4; ++p) {
        int idx = tid + p*256;
        int row = idx >> 4, q = idx & 15;
        float4 v = *(const float4*)(Asrc + (size_t)(h*SQ + i0 + row)*DH + q*4);
        *(float4*)&As[row*K2P + q*4] = v;
    }
    #pragma unroll
    for (int p = 0; p < 4; ++p) {
        int idx = tid + p*256;
        int row = idx >> 4, q = idx & 15;
        float4 v = *(const float4*)(Wp + (size_t)(e0 + row)*HDIM + h*64 + q*4);
        *(float4*)&Bs2[row*K2P + q*4] = v;
    }
    __syncthreads();

    float acc[2][2][4];
    #pragma unroll
    for (int mt = 0; mt < 2; ++mt)
        #pragma unroll
        for (int nt = 0; nt < 2; ++nt)
            #pragma unroll
            for (int r = 0; r < 4; ++r) acc[mt][nt][r] = 0.f;

    #pragma unroll
    for (int ks = 0; ks < 8; ++ks) {
        int eo = ks * 8;
        unsigned bh[2][2], bl[2][2];
        #pragma unroll
        for (int nt = 0; nt < 2; ++nt) {
            int n = wx*16 + nt*8;
            split_tf32(Bs2[(n + gid)*K2P + eo + tig    ], bh[nt][0], bl[nt][0]);
            split_tf32(Bs2[(n + gid)*K2P + eo + tig + 4], bh[nt][1], bl[nt][1]);
        }
        #pragma unroll
        for (int mt = 0; mt < 2; ++mt) {
            int m = wy*32 + mt*16;
            unsigned ah[4], al[4];
            split_tf32(As[(m + gid    )*K2P + eo + tig    ], ah[0], al[0]);
            split_tf32(As[(m + gid + 8)*K2P + eo + tig    ], ah[1], al[1]);
            split_tf32(As[(m + gid    )*K2P + eo + tig + 4], ah[2], al[2]);
            split_tf32(As[(m + gid + 8)*K2P + eo + tig + 4], ah[3], al[3]);
            #pragma unroll
            for (int nt = 0; nt < 2; ++nt) {
                mma_tf32(acc[mt][nt], ah[0], ah[1], ah[2], ah[3], bh[nt][0], bh[nt][1]);
                mma_tf32(acc[mt][nt], ah[0], ah[1], ah[2], ah[3], bl[nt][0], bl[nt][1]);
                mma_tf32(acc[mt][nt], al[0], al[1], al[2], al[3], bh[nt][0], bh[nt][1]);
            }
        }
    }
    __syncthreads();

    #pragma unroll
    for (int mt = 0; mt < 2; ++mt) {
        #pragma unroll
        for (int nt = 0; nt < 2; ++nt) {
            int i = wy*32 + mt*16 + gid;
            int e = wx*16 + nt*8 + tig*2;
            *(float2*)&As[ i     *K2P + e] = make_float2(acc[mt][nt][0], acc[mt][nt][1]);
            *(float2*)&As[(i + 8)*K2P + e] = make_float2(acc[mt][nt][2], acc[mt][nt][3]);
        }
    }
    __syncthreads();
    #pragma unroll
    for (int p = 0; p < 4; ++p) {
        int idx = tid + p*256;
        int row = idx >> 4, q = idx & 15;
        float4 v = *(const float4*)&As[row*K2P + q*4];
        *(float4*)(g_qkW + (size_t)(i0 + row)*QKW_I_STRIDE + c*HDIM + e0 + q*4) = v;
    }
}

// ================= K2b: c2c[h][i][j], single-sync ========================
__global__ void k2b_c2c()
{
    __shared__ float2 A2[64*33];     // [dd][ii 0..31]
    __shared__ float  Bs[64*66];     // [dd][jj 0..63]
    int h  = blockIdx.z;
    int i0 = blockIdx.y * 32;
    int j0 = blockIdx.x * 64;
    int tid = threadIdx.x;

    #pragma unroll
    for (int p = 0; p < 8; ++p) {
        int idx = tid + p*256;
        int dd = idx & 63, ii = idx >> 6;
        float v = g_Q[(h*SQ + i0 + ii)*DH + dd];
        A2[dd*33 + ii] = make_float2(v, v);
    }
    #pragma unroll
    for (int p = 0; p < 16; ++p) {
        int idx = tid + p*256;
        int dd = idx & 63, jj = idx >> 6;
        Bs[dd*66 + jj] = g_K[(h*SQ + j0 + jj)*DH + dd];
    }
    __syncthreads();

    int ix = tid & 15, iy = tid >> 4;
    float2 acc[2][2];
    acc[0][0]=make_float2(0,0); acc[0][1]=make_float2(0,0);
    acc[1][0]=make_float2(0,0); acc[1][1]=make_float2(0,0);
    #pragma unroll 16
    for (int dd = 0; dd < 64; ++dd) {
        float2 a0 = A2[dd*33 + iy*2];
        float2 a1 = A2[dd*33 + iy*2 + 1];
        float2 b0 = *(const float2*)&Bs[dd*66 + ix*4];
        float2 b1 = *(const float2*)&Bs[dd*66 + ix*4 + 2];
        acc[0][0] = ffma2(a0, b0, acc[0][0]);
        acc[0][1] = ffma2(a0, b1, acc[0][1]);
        acc[1][0] = ffma2(a1, b0, acc[1][0]);
        acc[1][1] = ffma2(a1, b1, acc[1][1]);
    }
    #pragma unroll
    for (int r = 0; r < 2; ++r) {
        float* o = g_C2C + ((size_t)h*SQ + i0 + iy*2 + r)*SQ + j0 + ix*4;
        *(float2*)o       = acc[r][0];
        *(float2*)(o + 2) = acc[r][1];
    }
}

// ================= K3: pos contraction, tf32 MMA, pair-issue cp.async =====
// CTA (jb, i): OUT[i][c][jb*128 + j] = sum_e qkW[i][c][e] * pos[i][jb*128+j][e]
// e-chunk = 16 (compute); cp.async issued in PAIRS (32 e = full 128B line/row).
#define JW3 128                   // j rows per CTA
#define AP3 20                    // smem pitch (floats)
#define ASTG (JW3*AP3)            // 2560 floats per stage
#define BSTG (NC*AP3)             // 480 floats per stage
#define NCH3 48                   // 768/16 compute chunks
#define NG3  24                   // issue groups (2 chunks each)
#define EP3 132                   // epilogue [c][j] pitch

__global__ void __launch_bounds__(256, 4) k3_pos(const float* __restrict__ pos)
{
    __shared__ float As[4*ASTG];   // 40 KB
    __shared__ float Bs[4*BSTG];   // 7.5 KB
    int jb = blockIdx.x;           // 0..2
    int i  = blockIdx.y;           // 0..383
    int tid = threadIdx.x;         // 256 = 8 warps
    int warp = tid >> 5, lane = tid & 31;
    int gid = lane >> 2, tig = lane & 3;
    int j0w = warp * 16;

    const float* posi = pos + (size_t)i * (SQ*HDIM) + (size_t)jb * JW3 * HDIM;
    const float* wsrc = g_qkW + (size_t)i * QKW_I_STRIDE;

    float acc[3][4];
    #pragma unroll
    for (int ct = 0; ct < 3; ++ct)
        #pragma unroll
        for (int r = 0; r < 4; ++r) acc[ct][r] = 0.f;

    // issue group k = chunks {2k, 2k+1}; each row transfers a FULL 128B line
    auto issuePair = [&](int k) {
        int e0 = k * 32;
        int sA = (2*k) & 3;                // 0 or 2
        float* asb = As + sA*ASTG;
        float* bsb = Bs + sA*BSTG;
        #pragma unroll
        for (int p = 0; p < 4; ++p) {
            int idx = tid + p*256;         // 1024 = 128 rows * 8 x 16B (one line)
            int j = idx >> 3, q = idx & 7;
            cp16(asb + (q>>2)*ASTG + j*AP3 + (q&3)*4,
                 posi + (size_t)j*HDIM + e0 + q*4);
        }
        if (tid < 192) {                   // 24 c * 8 x 16B
            int c = tid >> 3, q = tid & 7;
            cp16(bsb + (q>>2)*BSTG + c*AP3 + (q&3)*4,
                 wsrc + (size_t)c*HDIM + e0 + q*4);
        }
    };

    issuePair(0); cp_commit();
    issuePair(1); cp_commit();

    for (int k = 0; k < NG3; ++k) {
        // pending groups here: {k, k+1} (just {k} on the last iteration)
        if (k < NG3-1) cp_wait<1>();       // completes group k (in-order)
        else           cp_wait<0>();
        __syncthreads();                   // group k's stages visible to all

        #pragma unroll
        for (int half = 0; half < 2; ++half) {
            int s = (2*k + half) & 3;
            const float* a = As + s*ASTG;
            const float* b = Bs + s*BSTG;
            #pragma unroll
            for (int ks = 0; ks < 2; ++ks) {
                int eo = ks * 8;
                unsigned a0 = __float_as_uint(a[(j0w + gid    )*AP3 + eo + tig    ]);
                unsigned a1 = __float_as_uint(a[(j0w + gid + 8)*AP3 + eo + tig    ]);
                unsigned a2 = __float_as_uint(a[(j0w + gid    )*AP3 + eo + tig + 4]);
                unsigned a3 = __float_as_uint(a[(j0w + gid + 8)*AP3 + eo + tig + 4]);
                #pragma unroll
                for (int ct = 0; ct < 3; ++ct) {
                    unsigned b0 = __float_as_uint(b[(ct*8 + gid)*AP3 + eo + tig    ]);
                    unsigned b1 = __float_as_uint(b[(ct*8 + gid)*AP3 + eo + tig + 4]);
                    mma_tf32(acc[ct], a0, a1, a2, a3, b0, b1);
                }
            }
        }
        __syncthreads();                   // all warps done with group k's stages
        if (k + 2 < NG3) { issuePair(k + 2); cp_commit(); }  // reuses those stages
    }

    // ---- epilogue: stage [c][j] in smem (reuse As stages 0-1), coalesced STG
    #pragma unroll
    for (int ct = 0; ct < 3; ++ct) {
        int c = ct*8 + tig*2;
        As[ c   *EP3 + j0w + gid    ] = acc[ct][0];
        As[(c+1)*EP3 + j0w + gid    ] = acc[ct][1];
        As[ c   *EP3 + j0w + gid + 8] = acc[ct][2];
        As[(c+1)*EP3 + j0w + gid + 8] = acc[ct][3];
    }
    __syncthreads();
    float* o_base = g_OUT + (size_t)i * OUT_I_STRIDE + jb*JW3;
    #pragma unroll
    for (int p = 0; p < 3; ++p) {
        int idx = tid + p*256;             // 24c * 32 float4 = 768
        int c = idx >> 5, j4 = (idx & 31) * 4;
        float4 v = *(const float4*)&As[c*EP3 + j4];
        *(float4*)(o_base + c*SQ + j4) = v;
    }
}

// ================= KS: fused scores assembly + softmax ====================
#define SPITCH 386
__global__ void __launch_bounds__(256) ks_fused(const float* __restrict__ mask)
{
    __shared__ float S[16*SPITCH];        // 24.7KB
    int ib = blockIdx.x, h = blockIdx.y;
    int i0 = ib * 16;
    int tid = threadIdx.x;

    #pragma unroll
    for (int p = 0; p < 24; ++p) {
        int idx = tid + p*256;
        int ii = idx / 384, j = idx % 384;
        float v = g_C2C[((size_t)h*SQ + i0 + ii)*SQ + j]
                + g_OUT[(size_t)(i0 + ii)*OUT_I_STRIDE + h*SQ + j]
                + g_kb[h*SQ + j];
        S[ii*SPITCH + j] = v * 0.125f + mask[j];
    }
    __syncthreads();

    {
        int ti = tid & 15, tj = tid >> 4;
        #pragma unroll
        for (int t = 0; t < 24; ++t) {
            int j = t*16 + tj;
            float v = g_OUT[(size_t)j*OUT_I_STRIDE + (12 + h)*SQ + i0 + ti];
            S[ti*SPITCH + j] += v * 0.125f;
        }
    }
    __syncthreads();

    int warp = tid >> 5, lane = tid & 31;
    #pragma unroll
    for (int w2 = 0; w2 < 2; ++w2) {
        int il = warp*2 + w2;
        const float* srow = &S[il*SPITCH];
        float x[12];
        float m = -1e30f;
        #pragma unroll
        for (int t = 0; t < 12; ++t) { x[t] = srow[lane + t*32]; m = fmaxf(m, x[t]); }
        #pragma unroll
        for (int o = 16; o; o >>= 1) m = fmaxf(m, __shfl_xor_sync(0xffffffffu, m, o));
        float ss = 0.f;
        #pragma unroll
        for (int t = 0; t < 12; ++t) { x[t] = __expf(x[t] - m); ss += x[t]; }
        #pragma unroll
        for (int o = 16; o; o >>= 1) ss += __shfl_xor_sync(0xffffffffu, ss, o);
        float inv = 1.f / ss;
        float* prow = g_P + ((size_t)h*SQ + i0 + il)*SQ;
        #pragma unroll
        for (int t = 0; t < 12; ++t) prow[lane + t*32] = x[t] * inv;
    }
}

// ================= K5: context = P @ V (32-row i-tiles, 144 CTAs) =========
__global__ void k5_pv(float* __restrict__ out)
{
    __shared__ float2 A2[16*33];     // [kk][ii 0..31] duplicated
    __shared__ float  Bs[16*64];
    int h  = blockIdx.y;
    int i0 = blockIdx.x * 32;
    int tid = threadIdx.x;
    int ix = tid & 15, iy = tid >> 4;

    float2 acc[2][2];
    acc[0][0]=make_float2(0,0); acc[0][1]=make_float2(0,0);
    acc[1][0]=make_float2(0,0); acc[1][1]=make_float2(0,0);

    for (int k0 = 0; k0 < SQ; k0 += 16) {
        __syncthreads();
        #pragma unroll
        for (int p = 0; p < 2; ++p) {
            int idx = tid + p*256;
            int kk = idx & 15, r = idx >> 4;
            float v = g_P[((size_t)h*SQ + i0 + r)*SQ + k0 + kk];
            A2[kk*33 + r] = make_float2(v, v);
        }
        #pragma unroll
        for (int p = 0; p < 4; ++p) {
            int idx = tid + p*256;
            int nn = idx & 63, kk = idx >> 6;
            Bs[kk*64 + nn] = g_V[(h*SQ + k0 + kk)*DH + nn];
        }
        __syncthreads();
        #pragma unroll
        for (int kk = 0; kk < 16; ++kk) {
            float2 b0 = *(const float2*)&Bs[kk*64 + ix*4];
            float2 b1 = *(const float2*)&Bs[kk*64 + ix*4 + 2];
            float2 a0 = A2[kk*33 + iy*2];
            float2 a1 = A2[kk*33 + iy*2 + 1];
            acc[0][0] = ffma2(a0, b0, acc[0][0]);
            acc[0][1] = ffma2(a0, b1, acc[0][1]);
            acc[1][0] = ffma2(a1, b0, acc[1][0]);
            acc[1][1] = ffma2(a1, b1, acc[1][1]);
        }
    }
    #pragma unroll
    for (int u = 0; u < 2; ++u) {
        int i = i0 + iy*2 + u;
        float* o = out + (size_t)i*HDIM + h*64 + ix*4;
        *(float2*)o       = acc[u][0];
        *(float2*)(o + 2) = acc[u][1];
    }
}

// ================= launch =================================================
extern "C" void kernel_launch(void* const* d_in, const int* in_sizes, int n_in,
                              void* d_out, int out_size)
{
    const float* hidden = (const float*)d_in[0];
    const float* mask   = (const float*)d_in[1];
    const float* pos    = (const float*)d_in[2];
    const float* Wq  = (const float*)d_in[3];
    const float* bq  = (const float*)d_in[4];
    const float* Wk  = (const float*)d_in[5];
    const float* bk  = (const float*)d_in[6];
    const float* Wv  = (const float*)d_in[7];
    const float* bv  = (const float*)d_in[8];
    const float* Wpk = (const float*)d_in[9];
    // d_in[10] = bpk: constant over j -> softmax-invariant -> cancels exactly
    const float* Wpq = (const float*)d_in[11];
    const float* bpq = (const float*)d_in[12];
    float* out = (float*)d_out;

    // k3_pos kept at 4th launch so the fixed ncu sample lands on it.
    k1_qkv<<<dim3(12, 6, 3), 256>>>(hidden, Wq, bq, Wk, bk, Wv, bv);
    k2_qkw<<<dim3(12, 6, 24), 256>>>(Wpk, Wpq);
    k1b_kb<<<12, 384>>>(bpq);
    k3_pos<<<dim3(3, 384), 256>>>(pos);
    k2b_c2c<<<dim3(6, 12, 12), 256>>>();
    ks_fused<<<dim3(24, 12), 256>>>(mask);
    k5_pv<<<dim3(12, 12), 256>>>(out);
}

// round 10
// speedup vs baseline: 1.9175x; 1.1367x over previous
#include <cuda_runtime.h>
#include <math.h>

#define SQ 384
#define HDIM 768
#define NHEAD 12
#define DH 64
#define NC 24
#define QKW_I_STRIDE (NC*HDIM)   // 18432
#define OUT_I_STRIDE (NC*SQ)     // 9216

// ---------------- scratch (device globals; no allocation allowed) ----------
__device__ float g_Q[NHEAD*SQ*DH];
__device__ float g_K[NHEAD*SQ*DH];
__device__ float g_V[NHEAD*SQ*DH];
__device__ float g_kb[NHEAD*SQ];
__device__ float g_WT[3*HDIM*HDIM];      // [z][n][k] = W_z[k][n] transposed
__device__ float g_qkW[SQ*NC*HDIM];      // [i][c][e]
__device__ float g_OUT[SQ*NC*SQ];        // [i][c][j]
__device__ float g_C2C[NHEAD*SQ*SQ];     // [h][i][j]
__device__ float g_P[NHEAD*SQ*SQ];       // probs

__device__ __forceinline__ float2 ffma2(float2 a, float2 b, float2 c) {
    unsigned long long ua = *reinterpret_cast<unsigned long long*>(&a);
    unsigned long long ub = *reinterpret_cast<unsigned long long*>(&b);
    unsigned long long uc = *reinterpret_cast<unsigned long long*>(&c);
    unsigned long long ud;
    asm("fma.rn.f32x2 %0, %1, %2, %3;" : "=l"(ud) : "l"(ua), "l"(ub), "l"(uc));
    return *reinterpret_cast<float2*>(&ud);
}

__device__ __forceinline__ void mma_tf32(float* d, unsigned a0, unsigned a1,
                                         unsigned a2, unsigned a3,
                                         unsigned b0, unsigned b1) {
    asm volatile(
        "mma.sync.aligned.m16n8k8.row.col.f32.tf32.tf32.f32 "
        "{%0,%1,%2,%3}, {%4,%5,%6,%7}, {%8,%9}, {%0,%1,%2,%3};"
        : "+f"(d[0]), "+f"(d[1]), "+f"(d[2]), "+f"(d[3])
        : "r"(a0), "r"(a1), "r"(a2), "r"(a3), "r"(b0), "r"(b1));
}

// split fp32 into tf32 hi + tf32 lo (3xTF32 error compensation)
__device__ __forceinline__ void split_tf32(float x, unsigned& hi, unsigned& lo) {
    unsigned h;
    asm("cvt.rna.tf32.f32 %0, %1;" : "=r"(h) : "f"(x));
    float r = x - __uint_as_float(h);
    unsigned l;
    asm("cvt.rna.tf32.f32 %0, %1;" : "=r"(l) : "f"(r));
    hi = h; lo = l;
}

__device__ __forceinline__ void cp16(void* dst_smem, const void* src_gmem) {
    unsigned d = (unsigned)__cvta_generic_to_shared(dst_smem);
    asm volatile("cp.async.ca.shared.global [%0], [%1], 16;" :: "r"(d), "l"(src_gmem));
}
__device__ __forceinline__ void cp_commit() {
    asm volatile("cp.async.commit_group;");
}
template <int N>
__device__ __forceinline__ void cp_wait() {
    asm volatile("cp.async.wait_group %0;" :: "n"(N));
}

// ================= KT: transpose Wq/Wk/Wv -> g_WT[z][n][k] ================
__global__ void kT_transpose(const float* __restrict__ Wq,
                             const float* __restrict__ Wk,
                             const float* __restrict__ Wv)
{
    __shared__ float t[32][33];
    int z = blockIdx.z;
    const float* W = (z==0) ? Wq : (z==1) ? Wk : Wv;
    float* WT = g_WT + (size_t)z*HDIM*HDIM;
    int n0 = blockIdx.x*32, k0 = blockIdx.y*32;
    int tx = threadIdx.x & 31, ty = threadIdx.x >> 5;   // 256 thr: ty 0..7
    #pragma unroll
    for (int r = 0; r < 32; r += 8)
        t[ty+r][tx] = W[(size_t)(k0+ty+r)*HDIM + n0 + tx];
    __syncthreads();
    #pragma unroll
    for (int r = 0; r < 32; r += 8)
        WT[(size_t)(n0+ty+r)*HDIM + k0 + tx] = t[tx][ty+r];
}

// ================= K1: QKV projections, 3xTF32 MMA + cp.async pipeline ====
// CTA (h, ib, z): out[z][h][i0..i0+63][0..63] = hidden[i][:] @ W_z[:, h*64+n] + b
#define K1AP 20
#define K1ASTG (64*K1AP)     // 1280 floats per stage
#define K1NG 24              // 768 / 32 k per group

__global__ void __launch_bounds__(256, 4) k1_qkv(const float* __restrict__ hidden,
                       const float* __restrict__ bq,
                       const float* __restrict__ bk,
                       const float* __restrict__ bv)
{
    __shared__ float As[4*K1ASTG];    // 20.5 KB (epilogue reuses: 64*68=4352 fl)
    __shared__ float Bs4[4*K1ASTG];   // 20.5 KB
    int h = blockIdx.x, ib = blockIdx.y, z = blockIdx.z;
    const float* b = (z==0) ? bq : (z==1) ? bk : bv;
    float* outp    = (z==0) ? g_Q : (z==1) ? g_K : g_V;
    int i0 = ib * 64;
    int tid = threadIdx.x, warp = tid >> 5, lane = tid & 31;
    int gid = lane >> 2, tig = lane & 3;
    int wy = warp & 3;        // i-tile (16 rows)
    int wx = warp >> 2;       // n-half (32 cols)

    const float* abase = hidden + (size_t)i0*HDIM;
    const float* bbase = g_WT + (size_t)z*HDIM*HDIM + (size_t)(h*64)*HDIM;

    float acc[4][4];
    #pragma unroll
    for (int nt = 0; nt < 4; ++nt)
        #pragma unroll
        for (int r = 0; r < 4; ++r) acc[nt][r] = 0.f;

    auto issuePair = [&](int k) {
        int e0 = k * 32;
        int sA = (2*k) & 3;
        float* as = As  + sA*K1ASTG;
        float* bs = Bs4 + sA*K1ASTG;
        #pragma unroll
        for (int p = 0; p < 2; ++p) {        // 512 cp16: 64 rows * 8 (full line)
            int idx = tid + p*256;
            int r = idx >> 3, q = idx & 7;
            cp16(as + (q>>2)*K1ASTG + r*K1AP + (q&3)*4, abase + (size_t)r*HDIM + e0 + q*4);
        }
        #pragma unroll
        for (int p = 0; p < 2; ++p) {
            int idx = tid + p*256;
            int r = idx >> 3, q = idx & 7;
            cp16(bs + (q>>2)*K1ASTG + r*K1AP + (q&3)*4, bbase + (size_t)r*HDIM + e0 + q*4);
        }
    };

    issuePair(0); cp_commit();
    issuePair(1); cp_commit();

    for (int k = 0; k < K1NG; ++k) {
        if (k < K1NG-1) cp_wait<1>(); else cp_wait<0>();
        __syncthreads();
        #pragma unroll
        for (int half = 0; half < 2; ++half) {
            int s = (2*k + half) & 3;
            const float* a   = As  + s*K1ASTG;
            const float* bsm = Bs4 + s*K1ASTG;
            #pragma unroll
            for (int ks = 0; ks < 2; ++ks) {
                int eo = ks * 8;
                int m = wy * 16;
                unsigned ah[4], al[4];
                split_tf32(a[(m+gid  )*K1AP + eo + tig    ], ah[0], al[0]);
                split_tf32(a[(m+gid+8)*K1AP + eo + tig    ], ah[1], al[1]);
                split_tf32(a[(m+gid  )*K1AP + eo + tig + 4], ah[2], al[2]);
                split_tf32(a[(m+gid+8)*K1AP + eo + tig + 4], ah[3], al[3]);
                #pragma unroll
                for (int nt = 0; nt < 4; ++nt) {
                    int n = wx*32 + nt*8;
                    unsigned bh0, bl0, bh1, bl1;
                    split_tf32(bsm[(n+gid)*K1AP + eo + tig    ], bh0, bl0);
                    split_tf32(bsm[(n+gid)*K1AP + eo + tig + 4], bh1, bl1);
                    mma_tf32(acc[nt], ah[0],ah[1],ah[2],ah[3], bh0, bh1);
                    mma_tf32(acc[nt], ah[0],ah[1],ah[2],ah[3], bl0, bl1);
                    mma_tf32(acc[nt], al[0],al[1],al[2],al[3], bh0, bh1);
                }
            }
        }
        __syncthreads();
        if (k + 2 < K1NG) { issuePair(k + 2); cp_commit(); }
    }

    // epilogue: stage [i][n] (pitch 68, reuse As), add bias, coalesced STG
    #pragma unroll
    for (int nt = 0; nt < 4; ++nt) {
        int r0 = wy*16 + gid, r1 = r0 + 8;
        int nc = wx*32 + nt*8 + tig*2;
        As[r0*68 + nc    ] = acc[nt][0];
        As[r0*68 + nc + 1] = acc[nt][1];
        As[r1*68 + nc    ] = acc[nt][2];
        As[r1*68 + nc + 1] = acc[nt][3];
    }
    __syncthreads();
    #pragma unroll
    for (int p = 0; p < 4; ++p) {
        int idx = tid + p*256;
        int row = idx >> 4, q = idx & 15;
        float4 v  = *(const float4*)&As[row*68 + q*4];
        float4 bb = *(const float4*)&b[h*64 + q*4];
        v.x += bb.x; v.y += bb.y; v.z += bb.z; v.w += bb.w;
        *(float4*)(outp + (size_t)(h*SQ + i0 + row)*DH + q*4) = v;
    }
}

// ================= K1b: kb[h][j] = k[h,j,:].bpq_h =========================
__global__ void k1b_kb(const float* __restrict__ bpq)
{
    int h = blockIdx.x, j = threadIdx.x;
    const float* kp = g_K + (h*SQ + j)*DH;
    const float* bp = bpq + h*64;
    float s = 0.f;
    #pragma unroll 8
    for (int d = 0; d < DH; ++d) s += kp[d]*bp[d];
    g_kb[h*SQ + j] = s;
}

// ================= K2: qkW[i][c][e], 3xTF32 (error-compensated) ===========
#define K2P 68    // smem pitch (floats); 68 mod 32 == 4 -> conflict-free frags
__global__ void __launch_bounds__(256) k2_qkw(const float* __restrict__ Wpk,
                                              const float* __restrict__ Wpq)
{
    __shared__ float As[64*K2P];    // [i][d]
    __shared__ float Bs2[64*K2P];   // [e][d]
    int eb = blockIdx.x;            // 0..11
    int ib = blockIdx.y;            // 0..5
    int c  = blockIdx.z;            // 0..23
    int h  = (c < 12) ? c : c - 12;
    const float* Asrc = (c < 12) ? g_Q : g_K;
    const float* Wp   = (c < 12) ? Wpk : Wpq;
    int i0 = ib * 64, e0 = eb * 64;
    int tid = threadIdx.x;
    int warp = tid >> 5, lane = tid & 31;
    int gid = lane >> 2, tig = lane & 3;
    int wy = warp >> 2;             // i-half (32 rows)
    int wx = warp & 3;              // e-quarter (16 cols)

    #pragma unroll
    for (int p = 0; p < 4; ++p) {
        int idx = tid + p*256;
        int row = idx >> 4, q = idx & 15;
        float4 v = *(const float4*)(Asrc + (size_t)(h*SQ + i0 + row)*DH + q*4);
        *(float4*)&As[row*K2P + q*4] = v;
    }
    #pragma unroll
    for (int p = 0; p < 4; ++p) {
        int idx = tid + p*256;
        int row = idx >> 4, q = idx & 15;
        float4 v = *(const float4*)(Wp + (size_t)(e0 + row)*HDIM + h*64 + q*4);
        *(float4*)&Bs2[row*K2P + q*4] = v;
    }
    __syncthreads();

    float acc[2][2][4];
    #pragma unroll
    for (int mt = 0; mt < 2; ++mt)
        #pragma unroll
        for (int nt = 0; nt < 2; ++nt)
            #pragma unroll
            for (int r = 0; r < 4; ++r) acc[mt][nt][r] = 0.f;

    #pragma unroll
    for (int ks = 0; ks < 8; ++ks) {
        int eo = ks * 8;
        unsigned bh[2][2], bl[2][2];
        #pragma unroll
        for (int nt = 0; nt < 2; ++nt) {
            int n = wx*16 + nt*8;
            split_tf32(Bs2[(n + gid)*K2P + eo + tig    ], bh[nt][0], bl[nt][0]);
            split_tf32(Bs2[(n + gid)*K2P + eo + tig + 4], bh[nt][1], bl[nt][1]);
        }
        #pragma unroll
        for (int mt = 0; mt < 2; ++mt) {
            int m = wy*32 + mt*16;
            unsigned ah[4], al[4];
            split_tf32(As[(m + gid    )*K2P + eo + tig    ], ah[0], al[0]);
            split_tf32(As[(m + gid + 8)*K2P + eo + tig    ], ah[1], al[1]);
            split_tf32(As[(m + gid    )*K2P + eo + tig + 4], ah[2], al[2]);
            split_tf32(As[(m + gid + 8)*K2P + eo + tig + 4], ah[3], al[3]);
            #pragma unroll
            for (int nt = 0; nt < 2; ++nt) {
                mma_tf32(acc[mt][nt], ah[0], ah[1], ah[2], ah[3], bh[nt][0], bh[nt][1]);
                mma_tf32(acc[mt][nt], ah[0], ah[1], ah[2], ah[3], bl[nt][0], bl[nt][1]);
                mma_tf32(acc[mt][nt], al[0], al[1], al[2], al[3], bh[nt][0], bh[nt][1]);
            }
        }
    }
    __syncthreads();

    #pragma unroll
    for (int mt = 0; mt < 2; ++mt) {
        #pragma unroll
        for (int nt = 0; nt < 2; ++nt) {
            int i = wy*32 + mt*16 + gid;
            int e = wx*16 + nt*8 + tig*2;
            *(float2*)&As[ i     *K2P + e] = make_float2(acc[mt][nt][0], acc[mt][nt][1]);
            *(float2*)&As[(i + 8)*K2P + e] = make_float2(acc[mt][nt][2], acc[mt][nt][3]);
        }
    }
    __syncthreads();
    #pragma unroll
    for (int p = 0; p < 4; ++p) {
        int idx = tid + p*256;
        int row = idx >> 4, q = idx & 15;
        float4 v = *(const float4*)&As[row*K2P + q*4];
        *(float4*)(g_qkW + (size_t)(i0 + row)*QKW_I_STRIDE + c*HDIM + e0 + q*4) = v;
    }
}

// ================= K2b: c2c[h][i][j], 3xTF32 MMA ==========================
// CTA (jb, ib, h): c2c[i0..63][j0..63] = Q[i][d] . K[j][d]
__global__ void __launch_bounds__(256) k2b_c2c()
{
    __shared__ float As2[64*K2P];
    __shared__ float Bs2[64*K2P];
    int jb = blockIdx.x, ib = blockIdx.y, h = blockIdx.z;
    int i0 = ib*64, j0 = jb*64;
    int tid = threadIdx.x, warp = tid >> 5, lane = tid & 31;
    int gid = lane >> 2, tig = lane & 3;
    int wy = warp & 3, wx = warp >> 2;

    #pragma unroll
    for (int p = 0; p < 4; ++p) {
        int idx = tid + p*256;
        int row = idx >> 4, q = idx & 15;
        *(float4*)&As2[row*K2P + q*4] = *(const float4*)(g_Q + (size_t)(h*SQ + i0 + row)*DH + q*4);
        *(float4*)&Bs2[row*K2P + q*4] = *(const float4*)(g_K + (size_t)(h*SQ + j0 + row)*DH + q*4);
    }
    __syncthreads();

    float acc[4][4];
    #pragma unroll
    for (int nt = 0; nt < 4; ++nt)
        #pragma unroll
        for (int r = 0; r < 4; ++r) acc[nt][r] = 0.f;

    #pragma unroll
    for (int ks = 0; ks < 8; ++ks) {
        int eo = ks * 8;
        int m = wy * 16;
        unsigned ah[4], al[4];
        split_tf32(As2[(m+gid  )*K2P + eo + tig    ], ah[0], al[0]);
        split_tf32(As2[(m+gid+8)*K2P + eo + tig    ], ah[1], al[1]);
        split_tf32(As2[(m+gid  )*K2P + eo + tig + 4], ah[2], al[2]);
        split_tf32(As2[(m+gid+8)*K2P + eo + tig + 4], ah[3], al[3]);
        #pragma unroll
        for (int nt = 0; nt < 4; ++nt) {
            int n = wx*32 + nt*8;
            unsigned bh0, bl0, bh1, bl1;
            split_tf32(Bs2[(n+gid)*K2P + eo + tig    ], bh0, bl0);
            split_tf32(Bs2[(n+gid)*K2P + eo + tig + 4], bh1, bl1);
            mma_tf32(acc[nt], ah[0],ah[1],ah[2],ah[3], bh0, bh1);
            mma_tf32(acc[nt], ah[0],ah[1],ah[2],ah[3], bl0, bl1);
            mma_tf32(acc[nt], al[0],al[1],al[2],al[3], bh0, bh1);
        }
    }
    __syncthreads();

    #pragma unroll
    for (int nt = 0; nt < 4; ++nt) {
        int r0 = wy*16 + gid, r1 = r0 + 8;
        int nc = wx*32 + nt*8 + tig*2;
        As2[r0*K2P + nc    ] = acc[nt][0];
        As2[r0*K2P + nc + 1] = acc[nt][1];
        As2[r1*K2P + nc    ] = acc[nt][2];
        As2[r1*K2P + nc + 1] = acc[nt][3];
    }
    __syncthreads();
    #pragma unroll
    for (int p = 0; p < 4; ++p) {
        int idx = tid + p*256;
        int row = idx >> 4, q = idx & 15;
        float4 v = *(const float4*)&As2[row*K2P + q*4];
        *(float4*)(g_C2C + ((size_t)h*SQ + i0 + row)*SQ + j0 + q*4) = v;
    }
}

// ================= K3: pos contraction, tf32 MMA, pair-issue cp.async =====
#define JW3 128                   // j rows per CTA
#define AP3 20                    // smem pitch (floats)
#define ASTG (JW3*AP3)            // 2560 floats per stage
#define BSTG (NC*AP3)             // 480 floats per stage
#define NCH3 48                   // 768/16 compute chunks
#define NG3  24                   // issue groups (2 chunks each)
#define EP3 132                   // epilogue [c][j] pitch

__global__ void __launch_bounds__(256, 4) k3_pos(const float* __restrict__ pos)
{
    __shared__ float As[4*ASTG];   // 40 KB
    __shared__ float Bs[4*BSTG];   // 7.5 KB
    int jb = blockIdx.x;           // 0..2
    int i  = blockIdx.y;           // 0..383
    int tid = threadIdx.x;         // 256 = 8 warps
    int warp = tid >> 5, lane = tid & 31;
    int gid = lane >> 2, tig = lane & 3;
    int j0w = warp * 16;

    const float* posi = pos + (size_t)i * (SQ*HDIM) + (size_t)jb * JW3 * HDIM;
    const float* wsrc = g_qkW + (size_t)i * QKW_I_STRIDE;

    float acc[3][4];
    #pragma unroll
    for (int ct = 0; ct < 3; ++ct)
        #pragma unroll
        for (int r = 0; r < 4; ++r) acc[ct][r] = 0.f;

    auto issuePair = [&](int k) {
        int e0 = k * 32;
        int sA = (2*k) & 3;
        float* asb = As + sA*ASTG;
        float* bsb = Bs + sA*BSTG;
        #pragma unroll
        for (int p = 0; p < 4; ++p) {
            int idx = tid + p*256;
            int j = idx >> 3, q = idx & 7;
            cp16(asb + (q>>2)*ASTG + j*AP3 + (q&3)*4,
                 posi + (size_t)j*HDIM + e0 + q*4);
        }
        if (tid < 192) {
            int c = tid >> 3, q = tid & 7;
            cp16(bsb + (q>>2)*BSTG + c*AP3 + (q&3)*4,
                 wsrc + (size_t)c*HDIM + e0 + q*4);
        }
    };

    issuePair(0); cp_commit();
    issuePair(1); cp_commit();

    for (int k = 0; k < NG3; ++k) {
        if (k < NG3-1) cp_wait<1>();
        else           cp_wait<0>();
        __syncthreads();

        #pragma unroll
        for (int half = 0; half < 2; ++half) {
            int s = (2*k + half) & 3;
            const float* a = As + s*ASTG;
            const float* b = Bs + s*BSTG;
            #pragma unroll
            for (int ks = 0; ks < 2; ++ks) {
                int eo = ks * 8;
                unsigned a0 = __float_as_uint(a[(j0w + gid    )*AP3 + eo + tig    ]);
                unsigned a1 = __float_as_uint(a[(j0w + gid + 8)*AP3 + eo + tig    ]);
                unsigned a2 = __float_as_uint(a[(j0w + gid    )*AP3 + eo + tig + 4]);
                unsigned a3 = __float_as_uint(a[(j0w + gid + 8)*AP3 + eo + tig + 4]);
                #pragma unroll
                for (int ct = 0; ct < 3; ++ct) {
                    unsigned b0 = __float_as_uint(b[(ct*8 + gid)*AP3 + eo + tig    ]);
                    unsigned b1 = __float_as_uint(b[(ct*8 + gid)*AP3 + eo + tig + 4]);
                    mma_tf32(acc[ct], a0, a1, a2, a3, b0, b1);
                }
            }
        }
        __syncthreads();
        if (k + 2 < NG3) { issuePair(k + 2); cp_commit(); }
    }

    #pragma unroll
    for (int ct = 0; ct < 3; ++ct) {
        int c = ct*8 + tig*2;
        As[ c   *EP3 + j0w + gid    ] = acc[ct][0];
        As[(c+1)*EP3 + j0w + gid    ] = acc[ct][1];
        As[ c   *EP3 + j0w + gid + 8] = acc[ct][2];
        As[(c+1)*EP3 + j0w + gid + 8] = acc[ct][3];
    }
    __syncthreads();
    float* o_base = g_OUT + (size_t)i * OUT_I_STRIDE + jb*JW3;
    #pragma unroll
    for (int p = 0; p < 3; ++p) {
        int idx = tid + p*256;
        int c = idx >> 5, j4 = (idx & 31) * 4;
        float4 v = *(const float4*)&As[c*EP3 + j4];
        *(float4*)(o_base + c*SQ + j4) = v;
    }
}

// ================= KS: fused scores assembly + softmax ====================
#define SPITCH 386
__global__ void __launch_bounds__(256) ks_fused(const float* __restrict__ mask)
{
    __shared__ float S[16*SPITCH];        // 24.7KB
    int ib = blockIdx.x, h = blockIdx.y;
    int i0 = ib * 16;
    int tid = threadIdx.x;

    #pragma unroll
    for (int p = 0; p < 24; ++p) {
        int idx = tid + p*256;
        int ii = idx / 384, j = idx % 384;
        float v = g_C2C[((size_t)h*SQ + i0 + ii)*SQ + j]
                + g_OUT[(size_t)(i0 + ii)*OUT_I_STRIDE + h*SQ + j]
                + g_kb[h*SQ + j];
        S[ii*SPITCH + j] = v * 0.125f + mask[j];
    }
    __syncthreads();

    {
        int ti = tid & 15, tj = tid >> 4;
        #pragma unroll
        for (int t = 0; t < 24; ++t) {
            int j = t*16 + tj;
            float v = g_OUT[(size_t)j*OUT_I_STRIDE + (12 + h)*SQ + i0 + ti];
            S[ti*SPITCH + j] += v * 0.125f;
        }
    }
    __syncthreads();

    int warp = tid >> 5, lane = tid & 31;
    #pragma unroll
    for (int w2 = 0; w2 < 2; ++w2) {
        int il = warp*2 + w2;
        const float* srow = &S[il*SPITCH];
        float x[12];
        float m = -1e30f;
        #pragma unroll
        for (int t = 0; t < 12; ++t) { x[t] = srow[lane + t*32]; m = fmaxf(m, x[t]); }
        #pragma unroll
        for (int o = 16; o; o >>= 1) m = fmaxf(m, __shfl_xor_sync(0xffffffffu, m, o));
        float ss = 0.f;
        #pragma unroll
        for (int t = 0; t < 12; ++t) { x[t] = __expf(x[t] - m); ss += x[t]; }
        #pragma unroll
        for (int o = 16; o; o >>= 1) ss += __shfl_xor_sync(0xffffffffu, ss, o);
        float inv = 1.f / ss;
        float* prow = g_P + ((size_t)h*SQ + i0 + il)*SQ;
        #pragma unroll
        for (int t = 0; t < 12; ++t) prow[lane + t*32] = x[t] * inv;
    }
}

// ================= K5: context = P @ V (32-row i-tiles, 144 CTAs) =========
__global__ void k5_pv(float* __restrict__ out)
{
    __shared__ float2 A2[16*33];
    __shared__ float  Bs[16*64];
    int h  = blockIdx.y;
    int i0 = blockIdx.x * 32;
    int tid = threadIdx.x;
    int ix = tid & 15, iy = tid >> 4;

    float2 acc[2][2];
    acc[0][0]=make_float2(0,0); acc[0][1]=make_float2(0,0);
    acc[1][0]=make_float2(0,0); acc[1][1]=make_float2(0,0);

    for (int k0 = 0; k0 < SQ; k0 += 16) {
        __syncthreads();
        #pragma unroll
        for (int p = 0; p < 2; ++p) {
            int idx = tid + p*256;
            int kk = idx & 15, r = idx >> 4;
            float v = g_P[((size_t)h*SQ + i0 + r)*SQ + k0 + kk];
            A2[kk*33 + r] = make_float2(v, v);
        }
        #pragma unroll
        for (int p = 0; p < 4; ++p) {
            int idx = tid + p*256;
            int nn = idx & 63, kk = idx >> 6;
            Bs[kk*64 + nn] = g_V[(h*SQ + k0 + kk)*DH + nn];
        }
        __syncthreads();
        #pragma unroll
        for (int kk = 0; kk < 16; ++kk) {
            float2 b0 = *(const float2*)&Bs[kk*64 + ix*4];
            float2 b1 = *(const float2*)&Bs[kk*64 + ix*4 + 2];
            float2 a0 = A2[kk*33 + iy*2];
            float2 a1 = A2[kk*33 + iy*2 + 1];
            acc[0][0] = ffma2(a0, b0, acc[0][0]);
            acc[0][1] = ffma2(a0, b1, acc[0][1]);
            acc[1][0] = ffma2(a1, b0, acc[1][0]);
            acc[1][1] = ffma2(a1, b1, acc[1][1]);
        }
    }
    #pragma unroll
    for (int u = 0; u < 2; ++u) {
        int i = i0 + iy*2 + u;
        float* o = out + (size_t)i*HDIM + h*64 + ix*4;
        *(float2*)o       = acc[u][0];
        *(float2*)(o + 2) = acc[u][1];
    }
}

// ================= launch =================================================
extern "C" void kernel_launch(void* const* d_in, const int* in_sizes, int n_in,
                              void* d_out, int out_size)
{
    const float* hidden = (const float*)d_in[0];
    const float* mask   = (const float*)d_in[1];
    const float* pos    = (const float*)d_in[2];
    const float* Wq  = (const float*)d_in[3];
    const float* bq  = (const float*)d_in[4];
    const float* Wk  = (const float*)d_in[5];
    const float* bk  = (const float*)d_in[6];
    const float* Wv  = (const float*)d_in[7];
    const float* bv  = (const float*)d_in[8];
    const float* Wpk = (const float*)d_in[9];
    // d_in[10] = bpk: constant over j -> softmax-invariant -> cancels exactly
    const float* Wpq = (const float*)d_in[11];
    const float* bpq = (const float*)d_in[12];
    float* out = (float*)d_out;

    // k3_pos kept at 4th launch so the fixed ncu sample lands on it.
    kT_transpose<<<dim3(24, 24, 3), 256>>>(Wq, Wk, Wv);
    k1_qkv<<<dim3(12, 6, 3), 256>>>(hidden, bq, bk, bv);
    k2_qkw<<<dim3(12, 6, 24), 256>>>(Wpk, Wpq);
    k3_pos<<<dim3(3, 384), 256>>>(pos);
    k1b_kb<<<12, 384>>>(bpq);
    k2b_c2c<<<dim3(6, 6, 12), 256>>>();
    ks_fused<<<dim3(24, 12), 256>>>(mask);
    k5_pv<<<dim3(12, 12), 256>>>(out);
}

// round 11
// speedup vs baseline: 2.0280x; 1.0576x over previous
#include <cuda_runtime.h>
#include <math.h>

#define SQ 384
#define HDIM 768
#define NHEAD 12
#define DH 64
#define NC 24
#define QKW_I_STRIDE (NC*HDIM)   // 18432
#define OUT_I_STRIDE (NC*SQ)     // 9216

// ---------------- scratch (device globals; no allocation allowed) ----------
__device__ float g_Q[NHEAD*SQ*DH];
__device__ float g_K[NHEAD*SQ*DH];
__device__ float g_V[NHEAD*SQ*DH];
__device__ float g_VT[NHEAD*DH*SQ];      // [h][d][j]  (V transposed, bias added)
__device__ float g_kb[NHEAD*SQ];
__device__ float g_WT[3*HDIM*HDIM];      // [z][n][k] = W_z[k][n] transposed
__device__ float g_qkW[SQ*NC*HDIM];      // [i][c][e]
__device__ float g_OUT[SQ*NC*SQ];        // [i][c][j]
__device__ float g_C2C[NHEAD*SQ*SQ];     // [h][i][j]
__device__ float g_P[NHEAD*SQ*SQ];       // probs

__device__ __forceinline__ void mma_tf32(float* d, unsigned a0, unsigned a1,
                                         unsigned a2, unsigned a3,
                                         unsigned b0, unsigned b1) {
    asm volatile(
        "mma.sync.aligned.m16n8k8.row.col.f32.tf32.tf32.f32 "
        "{%0,%1,%2,%3}, {%4,%5,%6,%7}, {%8,%9}, {%0,%1,%2,%3};"
        : "+f"(d[0]), "+f"(d[1]), "+f"(d[2]), "+f"(d[3])
        : "r"(a0), "r"(a1), "r"(a2), "r"(a3), "r"(b0), "r"(b1));
}

// split fp32 into tf32 hi + tf32 lo (3xTF32 error compensation)
__device__ __forceinline__ void split_tf32(float x, unsigned& hi, unsigned& lo) {
    unsigned h;
    asm("cvt.rna.tf32.f32 %0, %1;" : "=r"(h) : "f"(x));
    float r = x - __uint_as_float(h);
    unsigned l;
    asm("cvt.rna.tf32.f32 %0, %1;" : "=r"(l) : "f"(r));
    hi = h; lo = l;
}

__device__ __forceinline__ void cp16(void* dst_smem, const void* src_gmem) {
    unsigned d = (unsigned)__cvta_generic_to_shared(dst_smem);
    asm volatile("cp.async.ca.shared.global [%0], [%1], 16;" :: "r"(d), "l"(src_gmem));
}
__device__ __forceinline__ void cp_commit() {
    asm volatile("cp.async.commit_group;");
}
template <int N>
__device__ __forceinline__ void cp_wait() {
    asm volatile("cp.async.wait_group %0;" :: "n"(N));
}

// ================= KT: transpose Wq/Wk/Wv -> g_WT[z][n][k] ================
__global__ void kT_transpose(const float* __restrict__ Wq,
                             const float* __restrict__ Wk,
                             const float* __restrict__ Wv)
{
    __shared__ float t[32][33];
    int z = blockIdx.z;
    const float* W = (z==0) ? Wq : (z==1) ? Wk : Wv;
    float* WT = g_WT + (size_t)z*HDIM*HDIM;
    int n0 = blockIdx.x*32, k0 = blockIdx.y*32;
    int tx = threadIdx.x & 31, ty = threadIdx.x >> 5;   // 256 thr: ty 0..7
    #pragma unroll
    for (int r = 0; r < 32; r += 8)
        t[ty+r][tx] = W[(size_t)(k0+ty+r)*HDIM + n0 + tx];
    __syncthreads();
    #pragma unroll
    for (int r = 0; r < 32; r += 8)
        WT[(size_t)(n0+ty+r)*HDIM + k0 + tx] = t[tx][ty+r];
}

// ================= K1: QKV projections, 3xTF32 MMA + cp.async pipeline ====
#define K1AP 20
#define K1ASTG (64*K1AP)     // 1280 floats per stage
#define K1NG 24              // 768 / 32 k per group

__global__ void __launch_bounds__(256, 4) k1_qkv(const float* __restrict__ hidden,
                       const float* __restrict__ bq,
                       const float* __restrict__ bk,
                       const float* __restrict__ bv)
{
    __shared__ float As[4*K1ASTG];    // 20.5 KB (epilogue reuses: 64*68=4352 fl)
    __shared__ float Bs4[4*K1ASTG];   // 20.5 KB
    int h = blockIdx.x, ib = blockIdx.y, z = blockIdx.z;
    const float* b = (z==0) ? bq : (z==1) ? bk : bv;
    float* outp    = (z==0) ? g_Q : (z==1) ? g_K : g_V;
    int i0 = ib * 64;
    int tid = threadIdx.x, warp = tid >> 5, lane = tid & 31;
    int gid = lane >> 2, tig = lane & 3;
    int wy = warp & 3;        // i-tile (16 rows)
    int wx = warp >> 2;       // n-half (32 cols)

    const float* abase = hidden + (size_t)i0*HDIM;
    const float* bbase = g_WT + (size_t)z*HDIM*HDIM + (size_t)(h*64)*HDIM;

    float acc[4][4];
    #pragma unroll
    for (int nt = 0; nt < 4; ++nt)
        #pragma unroll
        for (int r = 0; r < 4; ++r) acc[nt][r] = 0.f;

    auto issuePair = [&](int k) {
        int e0 = k * 32;
        int sA = (2*k) & 3;
        float* as = As  + sA*K1ASTG;
        float* bs = Bs4 + sA*K1ASTG;
        #pragma unroll
        for (int p = 0; p < 2; ++p) {
            int idx = tid + p*256;
            int r = idx >> 3, q = idx & 7;
            cp16(as + (q>>2)*K1ASTG + r*K1AP + (q&3)*4, abase + (size_t)r*HDIM + e0 + q*4);
        }
        #pragma unroll
        for (int p = 0; p < 2; ++p) {
            int idx = tid + p*256;
            int r = idx >> 3, q = idx & 7;
            cp16(bs + (q>>2)*K1ASTG + r*K1AP + (q&3)*4, bbase + (size_t)r*HDIM + e0 + q*4);
        }
    };

    issuePair(0); cp_commit();
    issuePair(1); cp_commit();

    for (int k = 0; k < K1NG; ++k) {
        if (k < K1NG-1) cp_wait<1>(); else cp_wait<0>();
        __syncthreads();
        #pragma unroll
        for (int half = 0; half < 2; ++half) {
            int s = (2*k + half) & 3;
            const float* a   = As  + s*K1ASTG;
            const float* bsm = Bs4 + s*K1ASTG;
            #pragma unroll
            for (int ks = 0; ks < 2; ++ks) {
                int eo = ks * 8;
                int m = wy * 16;
                unsigned ah[4], al[4];
                split_tf32(a[(m+gid  )*K1AP + eo + tig    ], ah[0], al[0]);
                split_tf32(a[(m+gid+8)*K1AP + eo + tig    ], ah[1], al[1]);
                split_tf32(a[(m+gid  )*K1AP + eo + tig + 4], ah[2], al[2]);
                split_tf32(a[(m+gid+8)*K1AP + eo + tig + 4], ah[3], al[3]);
                #pragma unroll
                for (int nt = 0; nt < 4; ++nt) {
                    int n = wx*32 + nt*8;
                    unsigned bh0, bl0, bh1, bl1;
                    split_tf32(bsm[(n+gid)*K1AP + eo + tig    ], bh0, bl0);
                    split_tf32(bsm[(n+gid)*K1AP + eo + tig + 4], bh1, bl1);
                    mma_tf32(acc[nt], ah[0],ah[1],ah[2],ah[3], bh0, bh1);
                    mma_tf32(acc[nt], ah[0],ah[1],ah[2],ah[3], bl0, bl1);
                    mma_tf32(acc[nt], al[0],al[1],al[2],al[3], bh0, bh1);
                }
            }
        }
        __syncthreads();
        if (k + 2 < K1NG) { issuePair(k + 2); cp_commit(); }
    }

    // epilogue: stage [i][n] (pitch 68, reuse As), add bias, coalesced STG
    #pragma unroll
    for (int nt = 0; nt < 4; ++nt) {
        int r0 = wy*16 + gid, r1 = r0 + 8;
        int nc = wx*32 + nt*8 + tig*2;
        As[r0*68 + nc    ] = acc[nt][0];
        As[r0*68 + nc + 1] = acc[nt][1];
        As[r1*68 + nc    ] = acc[nt][2];
        As[r1*68 + nc + 1] = acc[nt][3];
    }
    __syncthreads();
    #pragma unroll
    for (int p = 0; p < 4; ++p) {
        int idx = tid + p*256;
        int row = idx >> 4, q = idx & 15;
        float4 v  = *(const float4*)&As[row*68 + q*4];
        float4 bb = *(const float4*)&b[h*64 + q*4];
        v.x += bb.x; v.y += bb.y; v.z += bb.z; v.w += bb.w;
        *(float4*)(outp + (size_t)(h*SQ + i0 + row)*DH + q*4) = v;
    }
    // extra: V transposed (bias included) for k5's MMA B-operand
    if (z == 2) {
        #pragma unroll
        for (int p = 0; p < 16; ++p) {
            int idx = tid + p*256;          // 4096 = 64n * 64i
            int n = idx >> 6, ii = idx & 63;
            g_VT[(size_t)(h*64 + n)*SQ + i0 + ii] = As[ii*68 + n] + b[h*64 + n];
        }
    }
}

// ================= K1b: kb[h][j] = k[h,j,:].bpq_h =========================
__global__ void k1b_kb(const float* __restrict__ bpq)
{
    int h = blockIdx.x, j = threadIdx.x;
    const float* kp = g_K + (h*SQ + j)*DH;
    const float* bp = bpq + h*64;
    float s = 0.f;
    #pragma unroll 8
    for (int d = 0; d < DH; ++d) s += kp[d]*bp[d];
    g_kb[h*SQ + j] = s;
}

// ================= K2: qkW[i][c][e], 3xTF32 (error-compensated) ===========
#define K2P 68    // smem pitch (floats); 68 mod 32 == 4 -> conflict-free frags
__global__ void __launch_bounds__(256) k2_qkw(const float* __restrict__ Wpk,
                                              const float* __restrict__ Wpq)
{
    __shared__ float As[64*K2P];    // [i][d]
    __shared__ float Bs2[64*K2P];   // [e][d]
    int eb = blockIdx.x;            // 0..11
    int ib = blockIdx.y;            // 0..5
    int c  = blockIdx.z;            // 0..23
    int h  = (c < 12) ? c : c - 12;
    const float* Asrc = (c < 12) ? g_Q : g_K;
    const float* Wp   = (c < 12) ? Wpk : Wpq;
    int i0 = ib * 64, e0 = eb * 64;
    int tid = threadIdx.x;
    int warp = tid >> 5, lane = tid & 31;
    int gid = lane >> 2, tig = lane & 3;
    int wy = warp >> 2;             // i-half (32 rows)
    int wx = warp & 3;              // e-quarter (16 cols)

    #pragma unroll
    for (int p = 0; p < 4; ++p) {
        int idx = tid + p*256;
        int row = idx >> 4, q = idx & 15;
        float4 v = *(const float4*)(Asrc + (size_t)(h*SQ + i0 + row)*DH + q*4);
        *(float4*)&As[row*K2P + q*4] = v;
    }
    #pragma unroll
    for (int p = 0; p < 4; ++p) {
        int idx = tid + p*256;
        int row = idx >> 4, q = idx & 15;
        float4 v = *(const float4*)(Wp + (size_t)(e0 + row)*HDIM + h*64 + q*4);
        *(float4*)&Bs2[row*K2P + q*4] = v;
    }
    __syncthreads();

    float acc[2][2][4];
    #pragma unroll
    for (int mt = 0; mt < 2; ++mt)
        #pragma unroll
        for (int nt = 0; nt < 2; ++nt)
            #pragma unroll
            for (int r = 0; r < 4; ++r) acc[mt][nt][r] = 0.f;

    #pragma unroll
    for (int ks = 0; ks < 8; ++ks) {
        int eo = ks * 8;
        unsigned bh[2][2], bl[2][2];
        #pragma unroll
        for (int nt = 0; nt < 2; ++nt) {
            int n = wx*16 + nt*8;
            split_tf32(Bs2[(n + gid)*K2P + eo + tig    ], bh[nt][0], bl[nt][0]);
            split_tf32(Bs2[(n + gid)*K2P + eo + tig + 4], bh[nt][1], bl[nt][1]);
        }
        #pragma unroll
        for (int mt = 0; mt < 2; ++mt) {
            int m = wy*32 + mt*16;
            unsigned ah[4], al[4];
            split_tf32(As[(m + gid    )*K2P + eo + tig    ], ah[0], al[0]);
            split_tf32(As[(m + gid + 8)*K2P + eo + tig    ], ah[1], al[1]);
            split_tf32(As[(m + gid    )*K2P + eo + tig + 4], ah[2], al[2]);
            split_tf32(As[(m + gid + 8)*K2P + eo + tig + 4], ah[3], al[3]);
            #pragma unroll
            for (int nt = 0; nt < 2; ++nt) {
                mma_tf32(acc[mt][nt], ah[0], ah[1], ah[2], ah[3], bh[nt][0], bh[nt][1]);
                mma_tf32(acc[mt][nt], ah[0], ah[1], ah[2], ah[3], bl[nt][0], bl[nt][1]);
                mma_tf32(acc[mt][nt], al[0], al[1], al[2], al[3], bh[nt][0], bh[nt][1]);
            }
        }
    }
    __syncthreads();

    #pragma unroll
    for (int mt = 0; mt < 2; ++mt) {
        #pragma unroll
        for (int nt = 0; nt < 2; ++nt) {
            int i = wy*32 + mt*16 + gid;
            int e = wx*16 + nt*8 + tig*2;
            *(float2*)&As[ i     *K2P + e] = make_float2(acc[mt][nt][0], acc[mt][nt][1]);
            *(float2*)&As[(i + 8)*K2P + e] = make_float2(acc[mt][nt][2], acc[mt][nt][3]);
        }
    }
    __syncthreads();
    #pragma unroll
    for (int p = 0; p < 4; ++p) {
        int idx = tid + p*256;
        int row = idx >> 4, q = idx & 15;
        float4 v = *(const float4*)&As[row*K2P + q*4];
        *(float4*)(g_qkW + (size_t)(i0 + row)*QKW_I_STRIDE + c*HDIM + e0 + q*4) = v;
    }
}

// ================= K2b: c2c[h][i][j], 3xTF32 MMA ==========================
__global__ void __launch_bounds__(256) k2b_c2c()
{
    __shared__ float As2[64*K2P];
    __shared__ float Bs2[64*K2P];
    int jb = blockIdx.x, ib = blockIdx.y, h = blockIdx.z;
    int i0 = ib*64, j0 = jb*64;
    int tid = threadIdx.x, warp = tid >> 5, lane = tid & 31;
    int gid = lane >> 2, tig = lane & 3;
    int wy = warp & 3, wx = warp >> 2;

    #pragma unroll
    for (int p = 0; p < 4; ++p) {
        int idx = tid + p*256;
        int row = idx >> 4, q = idx & 15;
        *(float4*)&As2[row*K2P + q*4] = *(const float4*)(g_Q + (size_t)(h*SQ + i0 + row)*DH + q*4);
        *(float4*)&Bs2[row*K2P + q*4] = *(const float4*)(g_K + (size_t)(h*SQ + j0 + row)*DH + q*4);
    }
    __syncthreads();

    float acc[4][4];
    #pragma unroll
    for (int nt = 0; nt < 4; ++nt)
        #pragma unroll
        for (int r = 0; r < 4; ++r) acc[nt][r] = 0.f;

    #pragma unroll
    for (int ks = 0; ks < 8; ++ks) {
        int eo = ks * 8;
        int m = wy * 16;
        unsigned ah[4], al[4];
        split_tf32(As2[(m+gid  )*K2P + eo + tig    ], ah[0], al[0]);
        split_tf32(As2[(m+gid+8)*K2P + eo + tig    ], ah[1], al[1]);
        split_tf32(As2[(m+gid  )*K2P + eo + tig + 4], ah[2], al[2]);
        split_tf32(As2[(m+gid+8)*K2P + eo + tig + 4], ah[3], al[3]);
        #pragma unroll
        for (int nt = 0; nt < 4; ++nt) {
            int n = wx*32 + nt*8;
            unsigned bh0, bl0, bh1, bl1;
            split_tf32(Bs2[(n+gid)*K2P + eo + tig    ], bh0, bl0);
            split_tf32(Bs2[(n+gid)*K2P + eo + tig + 4], bh1, bl1);
            mma_tf32(acc[nt], ah[0],ah[1],ah[2],ah[3], bh0, bh1);
            mma_tf32(acc[nt], ah[0],ah[1],ah[2],ah[3], bl0, bl1);
            mma_tf32(acc[nt], al[0],al[1],al[2],al[3], bh0, bh1);
        }
    }
    __syncthreads();

    #pragma unroll
    for (int nt = 0; nt < 4; ++nt) {
        int r0 = wy*16 + gid, r1 = r0 + 8;
        int nc = wx*32 + nt*8 + tig*2;
        As2[r0*K2P + nc    ] = acc[nt][0];
        As2[r0*K2P + nc + 1] = acc[nt][1];
        As2[r1*K2P + nc    ] = acc[nt][2];
        As2[r1*K2P + nc + 1] = acc[nt][3];
    }
    __syncthreads();
    #pragma unroll
    for (int p = 0; p < 4; ++p) {
        int idx = tid + p*256;
        int row = idx >> 4, q = idx & 15;
        float4 v = *(const float4*)&As2[row*K2P + q*4];
        *(float4*)(g_C2C + ((size_t)h*SQ + i0 + row)*SQ + j0 + q*4) = v;
    }
}

// ================= K3: pos contraction, tf32 MMA, pair-issue cp.async =====
#define JW3 128                   // j rows per CTA
#define AP3 20                    // smem pitch (floats)
#define ASTG (JW3*AP3)            // 2560 floats per stage
#define BSTG (NC*AP3)             // 480 floats per stage
#define NG3  24                   // issue groups (2 chunks each)
#define EP3 132                   // epilogue [c][j] pitch

__global__ void __launch_bounds__(256, 4) k3_pos(const float* __restrict__ pos)
{
    __shared__ float As[4*ASTG];   // 40 KB
    __shared__ float Bs[4*BSTG];   // 7.5 KB
    int jb = blockIdx.x;           // 0..2
    int i  = blockIdx.y;           // 0..383
    int tid = threadIdx.x;         // 256 = 8 warps
    int warp = tid >> 5, lane = tid & 31;
    int gid = lane >> 2, tig = lane & 3;
    int j0w = warp * 16;

    const float* posi = pos + (size_t)i * (SQ*HDIM) + (size_t)jb * JW3 * HDIM;
    const float* wsrc = g_qkW + (size_t)i * QKW_I_STRIDE;

    float acc[3][4];
    #pragma unroll
    for (int ct = 0; ct < 3; ++ct)
        #pragma unroll
        for (int r = 0; r < 4; ++r) acc[ct][r] = 0.f;

    auto issuePair = [&](int k) {
        int e0 = k * 32;
        int sA = (2*k) & 3;
        float* asb = As + sA*ASTG;
        float* bsb = Bs + sA*BSTG;
        #pragma unroll
        for (int p = 0; p < 4; ++p) {
            int idx = tid + p*256;
            int j = idx >> 3, q = idx & 7;
            cp16(asb + (q>>2)*ASTG + j*AP3 + (q&3)*4,
                 posi + (size_t)j*HDIM + e0 + q*4);
        }
        if (tid < 192) {
            int c = tid >> 3, q = tid & 7;
            cp16(bsb + (q>>2)*BSTG + c*AP3 + (q&3)*4,
                 wsrc + (size_t)c*HDIM + e0 + q*4);
        }
    };

    issuePair(0); cp_commit();
    issuePair(1); cp_commit();

    for (int k = 0; k < NG3; ++k) {
        if (k < NG3-1) cp_wait<1>();
        else           cp_wait<0>();
        __syncthreads();

        #pragma unroll
        for (int half = 0; half < 2; ++half) {
            int s = (2*k + half) & 3;
            const float* a = As + s*ASTG;
            const float* b = Bs + s*BSTG;
            #pragma unroll
            for (int ks = 0; ks < 2; ++ks) {
                int eo = ks * 8;
                unsigned a0 = __float_as_uint(a[(j0w + gid    )*AP3 + eo + tig    ]);
                unsigned a1 = __float_as_uint(a[(j0w + gid + 8)*AP3 + eo + tig    ]);
                unsigned a2 = __float_as_uint(a[(j0w + gid    )*AP3 + eo + tig + 4]);
                unsigned a3 = __float_as_uint(a[(j0w + gid + 8)*AP3 + eo + tig + 4]);
                #pragma unroll
                for (int ct = 0; ct < 3; ++ct) {
                    unsigned b0 = __float_as_uint(b[(ct*8 + gid)*AP3 + eo + tig    ]);
                    unsigned b1 = __float_as_uint(b[(ct*8 + gid)*AP3 + eo + tig + 4]);
                    mma_tf32(acc[ct], a0, a1, a2, a3, b0, b1);
                }
            }
        }
        __syncthreads();
        if (k + 2 < NG3) { issuePair(k + 2); cp_commit(); }
    }

    #pragma unroll
    for (int ct = 0; ct < 3; ++ct) {
        int c = ct*8 + tig*2;
        As[ c   *EP3 + j0w + gid    ] = acc[ct][0];
        As[(c+1)*EP3 + j0w + gid    ] = acc[ct][1];
        As[ c   *EP3 + j0w + gid + 8] = acc[ct][2];
        As[(c+1)*EP3 + j0w + gid + 8] = acc[ct][3];
    }
    __syncthreads();
    float* o_base = g_OUT + (size_t)i * OUT_I_STRIDE + jb*JW3;
    #pragma unroll
    for (int p = 0; p < 3; ++p) {
        int idx = tid + p*256;
        int c = idx >> 5, j4 = (idx & 31) * 4;
        float4 v = *(const float4*)&As[c*EP3 + j4];
        *(float4*)(o_base + c*SQ + j4) = v;
    }
}

// ================= KS: fused scores assembly + softmax ====================
#define SPITCH 386
__global__ void __launch_bounds__(256) ks_fused(const float* __restrict__ mask)
{
    __shared__ float S[16*SPITCH];        // 24.7KB
    int ib = blockIdx.x, h = blockIdx.y;
    int i0 = ib * 16;
    int tid = threadIdx.x;

    #pragma unroll
    for (int p = 0; p < 24; ++p) {
        int idx = tid + p*256;
        int ii = idx / 384, j = idx % 384;
        float v = g_C2C[((size_t)h*SQ + i0 + ii)*SQ + j]
                + g_OUT[(size_t)(i0 + ii)*OUT_I_STRIDE + h*SQ + j]
                + g_kb[h*SQ + j];
        S[ii*SPITCH + j] = v * 0.125f + mask[j];
    }
    __syncthreads();

    {
        int ti = tid & 15, tj = tid >> 4;
        #pragma unroll
        for (int t = 0; t < 24; ++t) {
            int j = t*16 + tj;
            float v = g_OUT[(size_t)j*OUT_I_STRIDE + (12 + h)*SQ + i0 + ti];
            S[ti*SPITCH + j] += v * 0.125f;
        }
    }
    __syncthreads();

    int warp = tid >> 5, lane = tid & 31;
    #pragma unroll
    for (int w2 = 0; w2 < 2; ++w2) {
        int il = warp*2 + w2;
        const float* srow = &S[il*SPITCH];
        float x[12];
        float m = -1e30f;
        #pragma unroll
        for (int t = 0; t < 12; ++t) { x[t] = srow[lane + t*32]; m = fmaxf(m, x[t]); }
        #pragma unroll
        for (int o = 16; o; o >>= 1) m = fmaxf(m, __shfl_xor_sync(0xffffffffu, m, o));
        float ss = 0.f;
        #pragma unroll
        for (int t = 0; t < 12; ++t) { x[t] = __expf(x[t] - m); ss += x[t]; }
        #pragma unroll
        for (int o = 16; o; o >>= 1) ss += __shfl_xor_sync(0xffffffffu, ss, o);
        float inv = 1.f / ss;
        float* prow = g_P + ((size_t)h*SQ + i0 + il)*SQ;
        #pragma unroll
        for (int t = 0; t < 12; ++t) prow[lane + t*32] = x[t] * inv;
    }
}

// ================= K5: context = P @ V^T via 3xTF32 MMA ===================
// CTA (ib, h): out[i0..i0+31][h*64..h*64+63] = P[h][i][j] . VT[h][n][j]
#define K5P 68
__global__ void __launch_bounds__(256) k5_pv(float* __restrict__ out)
{
    __shared__ float As5[32*K5P];   // [i][k]  8.7 KB
    __shared__ float Bs5[64*K5P];   // [n][k] 17.4 KB
    int ib = blockIdx.x, h = blockIdx.y;
    int i0 = ib * 32;
    int tid = threadIdx.x, warp = tid >> 5, lane = tid & 31;
    int gid = lane >> 2, tig = lane & 3;
    int wy = warp & 1;         // i-tile (16 rows)
    int wx = warp >> 1;        // n-block (16 cols), nt in {0,1}

    float acc[2][4];
    #pragma unroll
    for (int nt = 0; nt < 2; ++nt)
        #pragma unroll
        for (int r = 0; r < 4; ++r) acc[nt][r] = 0.f;

    for (int kc = 0; kc < 6; ++kc) {
        int k0 = kc * 64;
        __syncthreads();
        #pragma unroll
        for (int p = 0; p < 2; ++p) {
            int idx = tid + p*256;          // 512 float4 = 32 rows x 16
            int row = idx >> 4, q = idx & 15;
            *(float4*)&As5[row*K5P + q*4] =
                *(const float4*)(g_P + ((size_t)h*SQ + i0 + row)*SQ + k0 + q*4);
        }
        #pragma unroll
        for (int p = 0; p < 4; ++p) {
            int idx = tid + p*256;          // 1024 float4 = 64 rows x 16
            int row = idx >> 4, q = idx & 15;
            *(float4*)&Bs5[row*K5P + q*4] =
                *(const float4*)(g_VT + ((size_t)h*64 + row)*SQ + k0 + q*4);
        }
        __syncthreads();

        #pragma unroll
        for (int ks = 0; ks < 8; ++ks) {
            int eo = ks * 8;
            int m = wy * 16;
            unsigned ah[4], al[4];
            split_tf32(As5[(m+gid  )*K5P + eo + tig    ], ah[0], al[0]);
            split_tf32(As5[(m+gid+8)*K5P + eo + tig    ], ah[1], al[1]);
            split_tf32(As5[(m+gid  )*K5P + eo + tig + 4], ah[2], al[2]);
            split_tf32(As5[(m+gid+8)*K5P + eo + tig + 4], ah[3], al[3]);
            #pragma unroll
            for (int nt = 0; nt < 2; ++nt) {
                int n = wx*16 + nt*8;
                unsigned bh0, bl0, bh1, bl1;
                split_tf32(Bs5[(n+gid)*K5P + eo + tig    ], bh0, bl0);
                split_tf32(Bs5[(n+gid)*K5P + eo + tig + 4], bh1, bl1);
                mma_tf32(acc[nt], ah[0],ah[1],ah[2],ah[3], bh0, bh1);
                mma_tf32(acc[nt], ah[0],ah[1],ah[2],ah[3], bl0, bl1);
                mma_tf32(acc[nt], al[0],al[1],al[2],al[3], bh0, bh1);
            }
        }
    }
    __syncthreads();

    // stage [i 0..31][n 0..63] into As5-area (needs 32*68 floats, fits), STG
    #pragma unroll
    for (int nt = 0; nt < 2; ++nt) {
        int r0 = wy*16 + gid, r1 = r0 + 8;
        int nc = wx*16 + nt*8 + tig*2;
        As5[r0*K5P + nc    ] = acc[nt][0];
        As5[r0*K5P + nc + 1] = acc[nt][1];
        As5[r1*K5P + nc    ] = acc[nt][2];
        As5[r1*K5P + nc + 1] = acc[nt][3];
    }
    __syncthreads();
    #pragma unroll
    for (int p = 0; p < 2; ++p) {
        int idx = tid + p*256;
        int row = idx >> 4, q = idx & 15;
        float4 v = *(const float4*)&As5[row*K5P + q*4];
        *(float4*)(out + (size_t)(i0 + row)*HDIM + h*64 + q*4) = v;
    }
}

// ================= launch =================================================
extern "C" void kernel_launch(void* const* d_in, const int* in_sizes, int n_in,
                              void* d_out, int out_size)
{
    const float* hidden = (const float*)d_in[0];
    const float* mask   = (const float*)d_in[1];
    const float* pos    = (const float*)d_in[2];
    const float* Wq  = (const float*)d_in[3];
    const float* bq  = (const float*)d_in[4];
    const float* Wk  = (const float*)d_in[5];
    const float* bk  = (const float*)d_in[6];
    const float* Wv  = (const float*)d_in[7];
    const float* bv  = (const float*)d_in[8];
    const float* Wpk = (const float*)d_in[9];
    // d_in[10] = bpk: constant over j -> softmax-invariant -> cancels exactly
    const float* Wpq = (const float*)d_in[11];
    const float* bpq = (const float*)d_in[12];
    float* out = (float*)d_out;

    // k2_qkw placed 4th: ncu samples the 4th launch -> get its profile.
    kT_transpose<<<dim3(24, 24, 3), 256>>>(Wq, Wk, Wv);
    k1_qkv<<<dim3(12, 6, 3), 256>>>(hidden, bq, bk, bv);
    k1b_kb<<<12, 384>>>(bpq);
    k2_qkw<<<dim3(12, 6, 24), 256>>>(Wpk, Wpq);
    k3_pos<<<dim3(3, 384), 256>>>(pos);
    k2b_c2c<<<dim3(6, 6, 12), 256>>>();
    ks_fused<<<dim3(24, 12), 256>>>(mask);
    k5_pv<<<dim3(12, 12), 256>>>(out);
}